// round 12
// baseline (speedup 1.0000x reference)
#include <cuda_runtime.h>
#include <cuda_bf16.h>
#include <math.h>
#include <stdint.h>

#define NB 512
#define NT 128
#define NHE 512
#define NGE 2048
#define NZ 128
#define NHD 2048
#define NGD 8192
#define NOUTD 123
#define DATALD 129
#define DLD 133

#if !defined(__CUDA_ARCH__)
#define USE_TC 1
#elif defined(__CUDA_ARCH_FEAT_SM103_ALL) || defined(__CUDA_ARCH_FEAT_SM100_ALL)
#define USE_TC 1
#else
#define USE_TC 0
#endif

// ---------------- device scratch ----------------
__device__ __nv_bfloat16 g_dWhh_hi[NGD * NHD];
__device__ __nv_bfloat16 g_dWhh_lo[NGD * NHD];
__device__ __nv_bfloat16 g_eWf_hi[NGE * NHE];
__device__ __nv_bfloat16 g_eWf_lo[NGE * NHE];
__device__ __nv_bfloat16 g_eWb_hi[NGE * NHE];
__device__ __nv_bfloat16 g_eWb_lo[NGE * NHE];
__device__ __nv_bfloat16 g_eOut_hi[2 * NZ * 2 * NHE];
__device__ __nv_bfloat16 g_eOut_lo[2 * NZ * 2 * NHE];
__device__ __nv_bfloat16 g_initW_hi[2 * NHD * NZ];
__device__ __nv_bfloat16 g_initW_lo[2 * NHD * NZ];
__device__ __nv_bfloat16 g_zW_hi[NGD * NZ];
__device__ __nv_bfloat16 g_zW_lo[NGD * NZ];
__device__ __nv_bfloat16 g_outW_hi[NOUTD * NHD];
__device__ __nv_bfloat16 g_outW_lo[NOUTD * NHD];
__device__ float2 g_dWih2[NGD];

__device__ __nv_bfloat16 g_hn_hi[NB * 2 * NHE];
__device__ __nv_bfloat16 g_hn_lo[NB * 2 * NHE];
__device__ float g_ce[2 * NB * NHE];
__device__ float g_Ge[2 * NB * NGE];
__device__ float g_zml[NB * 2 * NZ];
__device__ __nv_bfloat16 g_z_hi[NB * NZ];
__device__ __nv_bfloat16 g_z_lo[NB * NZ];
__device__ float g_init[NB * 2 * NHD];
__device__ __nv_bfloat16 g_h0_hi[NB * NHD];
__device__ __nv_bfloat16 g_h0_lo[NB * NHD];
__device__ float g_cd[NB * NHD];
__device__ float g_zp[NB * NGD];
__device__ float g_G[NB * NGD];
__device__ __nv_bfloat16 g_hs_hi[(size_t)NB * NT * NHD];
__device__ __nv_bfloat16 g_hs_lo[(size_t)NB * NT * NHD];

// ---------------- helpers ----------------
__device__ __forceinline__ uint32_t smem_u32(const void* p) {
  uint32_t a;
  asm("{ .reg .u64 t; cvta.to.shared.u64 t, %1; cvt.u32.u64 %0, t; }" : "=r"(a) : "l"(p));
  return a;
}
__device__ __forceinline__ void cp16(uint32_t dst, const void* src, bool ok) {
  int sz = ok ? 16 : 0;
  asm volatile("cp.async.cg.shared.global [%0], [%1], 16, %2;\n"
               :: "r"(dst), "l"(src), "r"(sz) : "memory");
}
__device__ __forceinline__ void cp_commit() { asm volatile("cp.async.commit_group;" ::: "memory"); }
template <int N>
__device__ __forceinline__ void cp_wait() { asm volatile("cp.async.wait_group %0;" :: "n"(N) : "memory"); }

__device__ __forceinline__ float sigf(float x) {
  return __fdividef(1.0f, 1.0f + __expf(-x));
}
__device__ __forceinline__ float tanhfast(float x) {
  return 2.0f * sigf(2.0f * x) - 1.0f;
}
__device__ __forceinline__ void split_bf16(float x, __nv_bfloat16* hi, __nv_bfloat16* lo) {
  __nv_bfloat16 h = __float2bfloat16(x);
  *hi = h;
  *lo = __float2bfloat16(x - __bfloat162float(h));
}

struct GArg {
  const __nv_bfloat16 *Ahi, *Alo;  // [M][K] stride lda
  const __nv_bfloat16 *Whi, *Wlo;  // [N][K] packed
  const float *bias;
  const float *Cadd;
  float *C;
};

#define GS 197632u           // TN=256: 1024 + 4*49152
#define GS128 132096u        // TN=128: 1024 + 4*32768
#define GS64 99328u          // TN=64 : 1024 + 4*24576  (2 CTAs/SM)

#if USE_TC
// =====================================================================
// tcgen05 path — unified KC=32/SW64 4-stage pipelined GEMM
// =====================================================================
__device__ __forceinline__ uint32_t elect_one_pred() {
  uint32_t pred;
  asm volatile(
      "{\n\t.reg .pred p;\n\telect.sync _|p, 0xFFFFFFFF;\n\tselp.b32 %0, 1, 0, p;\n\t}"
      : "=r"(pred));
  return pred;
}
#define MBARRIER_INIT(addr, cnt) \
  asm volatile("mbarrier.init.shared.b64 [%0], %1;" :: "r"((uint32_t)(addr)), "r"((uint32_t)(cnt)) : "memory")
#define MBARRIER_WAIT_PARITY(addr, par) do {                                        \
  uint32_t _m = (uint32_t)(addr); uint32_t _p = (uint32_t)(par);                    \
  asm volatile("{\n\t.reg .pred P1;\n\t"                                            \
    "WL_%=:\n\t"                                                                    \
    "mbarrier.try_wait.parity.acquire.cta.shared::cta.b64 P1, [%0], %1, 0x989680;\n\t" \
    "@P1 bra.uni WD_%=;\n\t"                                                        \
    "bra.uni WL_%=;\n\t"                                                            \
    "WD_%=:\n\t}" :: "r"(_m), "r"(_p) : "memory");                                  \
} while (0)

#define TCGEN05_ALLOC(sm, n) \
  asm volatile("tcgen05.alloc.cta_group::1.sync.aligned.shared::cta.b32 [%0], %1;" \
               :: "r"((uint32_t)(sm)), "r"((uint32_t)(n)) : "memory")
#define TCGEN05_DEALLOC(t, n) \
  asm volatile("tcgen05.dealloc.cta_group::1.sync.aligned.b32 %0, %1;" :: "r"(t), "r"((uint32_t)(n)))
#define TCGEN05_RELINQ() \
  asm volatile("tcgen05.relinquish_alloc_permit.cta_group::1.sync.aligned;")
#define TCGEN05_COMMIT(mb) \
  asm volatile("tcgen05.commit.cta_group::1.mbarrier::arrive::one.shared::cluster.b64 [%0];" \
               :: "r"((uint32_t)(mb)) : "memory")
#define TCGEN05_FENCE_AFTER()  asm volatile("tcgen05.fence::after_thread_sync;" ::: "memory")
#define TCGEN05_FENCE_BEFORE() asm volatile("tcgen05.fence::before_thread_sync;" ::: "memory")
#define TCGEN05_WAIT_LD()      asm volatile("tcgen05.wait::ld.sync.aligned;" ::: "memory")
#define TCGEN05_LD_32X32B_X32(r, addr)                                            \
  asm volatile(                                                                   \
      "tcgen05.ld.sync.aligned.32x32b.x32.b32 "                                   \
      "{%0, %1, %2, %3, %4, %5, %6, %7, %8, %9, %10, %11, %12, %13, %14, %15, "   \
      " %16, %17, %18, %19, %20, %21, %22, %23, %24, %25, %26, %27, %28, %29, %30, %31}, [%32];" \
      : "=r"((r)[0]), "=r"((r)[1]), "=r"((r)[2]), "=r"((r)[3]),                   \
        "=r"((r)[4]), "=r"((r)[5]), "=r"((r)[6]), "=r"((r)[7]),                   \
        "=r"((r)[8]), "=r"((r)[9]), "=r"((r)[10]), "=r"((r)[11]),                 \
        "=r"((r)[12]), "=r"((r)[13]), "=r"((r)[14]), "=r"((r)[15]),               \
        "=r"((r)[16]), "=r"((r)[17]), "=r"((r)[18]), "=r"((r)[19]),               \
        "=r"((r)[20]), "=r"((r)[21]), "=r"((r)[22]), "=r"((r)[23]),               \
        "=r"((r)[24]), "=r"((r)[25]), "=r"((r)[26]), "=r"((r)[27]),               \
        "=r"((r)[28]), "=r"((r)[29]), "=r"((r)[30]), "=r"((r)[31])                \
      : "r"(addr))

static constexpr unsigned long long SMEM_DESC_BASE_SW64 =
    (4ull << 61) | (1ull << 46) | (32ull << 32) | (1ull << 16);
#define MAKE_SMEM_DESC64(a) (SMEM_DESC_BASE_SW64 | ((unsigned long long)((a) >> 4) & 0x3FFF))

template <int TN>
__device__ __forceinline__ void mma_cg1(uint32_t d, unsigned long long a,
                                        unsigned long long b, uint32_t en) {
  constexpr uint32_t idesc =
      (1u << 4) | (1u << 7) | (1u << 10) | ((TN / 8u) << 17) | (8u << 24);
  asm volatile(
      "{\n\t.reg .pred p;\n\tsetp.ne.u32 p, %4, 0;\n\t"
      "tcgen05.mma.cta_group::1.kind::f16 [%0], %1, %2, %3, {%5, %5, %5, %5}, p;\n\t}"
      :: "r"(d), "l"(a), "l"(b), "r"(idesc), "r"(en), "r"(0u) : "memory");
}

// KC=32/SW64 stage: Ahi@0(8K), Alo@8K, Bhi@16K(TN*64), Blo after
template <int TN>
__device__ __forceinline__ void load_stageP(
    uint32_t sbase, int stage, int ci, const GArg& g,
    size_t lda, int m0, int n0, int N, int K, int tid)
{
  const uint32_t stb = 16384u + (uint32_t)TN * 128u;
  const uint32_t base = sbase + (uint32_t)stage * stb;
  const int k0 = ci << 5;
#pragma unroll
  for (int it = 0; it < 2; ++it) {   // A: 128 rows x 4 chunks = 512
    int idx = tid + (it << 8);
    int row = idx >> 2, c = idx & 3;
    uint32_t off = (uint32_t)((row << 6) + (c << 4));
    off ^= ((off >> 3) & 0x30);
    size_t so = (size_t)(m0 + row) * lda + (size_t)k0 + (c << 3);
    cp16(base + off, g.Ahi + so, true);
    cp16(base + 8192u + off, g.Alo + so, true);
  }
#pragma unroll
  for (int it = 0; it < TN / 64; ++it) {  // B: TN rows x 4 chunks
    int idx = tid + (it << 8);
    int row = idx >> 2, c = idx & 3;
    int n = n0 + row;
    bool ok = (n < N);
    uint32_t off = (uint32_t)((row << 6) + (c << 4));
    off ^= ((off >> 3) & 0x30);
    size_t so = (size_t)(ok ? n : 0) * (size_t)K + (size_t)k0 + (c << 3);
    cp16(base + 16384u + off, g.Whi + so, ok);
    cp16(base + 16384u + (uint32_t)TN * 64u + off, g.Wlo + so, ok);
  }
  cp_commit();
}

template <int TN>
__device__ __forceinline__ void mma_chunkP(uint32_t sbase, int stage,
                                           uint32_t tmem, bool first) {
  const uint32_t stb = 16384u + (uint32_t)TN * 128u;
  uint32_t base = sbase + (uint32_t)stage * stb;
  unsigned long long dAh = MAKE_SMEM_DESC64(base);
  unsigned long long dAl = MAKE_SMEM_DESC64(base + 8192u);
  unsigned long long dBh = MAKE_SMEM_DESC64(base + 16384u);
  unsigned long long dBl = MAKE_SMEM_DESC64(base + 16384u + (uint32_t)TN * 64u);
#pragma unroll
  for (int ks = 0; ks < 2; ++ks) {
    unsigned long long o = (unsigned long long)(2 * ks);
    mma_cg1<TN>(tmem, dAh + o, dBh + o, (first && ks == 0) ? 0u : 1u);
    mma_cg1<TN>(tmem, dAh + o, dBl + o, 1u);
    mma_cg1<TN>(tmem, dAl + o, dBh + o, 1u);
  }
}

template <int TN>
__global__ void __launch_bounds__(256) gemm3(GArg a0, GArg a1, size_t lda,
                                             size_t ldc, int N, int K) {
  extern __shared__ __align__(1024) char smem[];
  const int tid = threadIdx.x;
  const uint32_t sb = smem_u32(smem);
  const GArg g = blockIdx.z ? a1 : a0;
  const int m0 = blockIdx.y * 128;
  const int n0 = blockIdx.x * TN;
  const int nch = K >> 5;            // K multiple of 32, nch >= 4

  if (tid == 0)
    for (int s = 0; s < 4; ++s) MBARRIER_INIT(sb + 16 + 8 * s, 1);
  if (tid < 32) TCGEN05_ALLOC(sb, TN);
  __syncthreads();
  uint32_t tmem;
  asm volatile("ld.shared.b32 %0, [%1];" : "=r"(tmem) : "r"(sb));

  load_stageP<TN>(sb + 1024u, 0, 0, g, lda, m0, n0, N, K, tid);
  load_stageP<TN>(sb + 1024u, 1, 1, g, lda, m0, n0, N, K, tid);
  load_stageP<TN>(sb + 1024u, 2, 2, g, lda, m0, n0, N, K, tid);

  for (int i = 0; i < nch; ++i) {
    const int s = i & 3;
    if (i >= 1) {                    // delayed issue: load chunk i+2
      int nc = i + 2;
      if (nc < nch) {
        if (nc >= 4) MBARRIER_WAIT_PARITY(sb + 16 + 8 * (nc & 3), ((nc - 4) >> 2) & 1);
        load_stageP<TN>(sb + 1024u, nc & 3, nc, g, lda, m0, n0, N, K, tid);
      } else cp_commit();
    }
    cp_wait<2>();
    asm volatile("fence.proxy.async.shared::cta;" ::: "memory");
    __syncthreads();
    if (tid < 32 && elect_one_pred()) {
      mma_chunkP<TN>(sb + 1024u, s, tmem, i == 0);
      TCGEN05_COMMIT(sb + 16 + 8 * s);
    }
  }
  MBARRIER_WAIT_PARITY(sb + 16 + 8 * ((nch - 1) & 3), ((nch - 1) >> 2) & 1);
  TCGEN05_FENCE_AFTER();

  {
    const int wq = (tid >> 5) & 3, wg = tid >> 7, lane = tid & 31;
    const size_t m = (size_t)m0 + (size_t)(wq * 32 + lane);
    float* crow = g.C + m * ldc;
    const float* arow = g.Cadd ? (g.Cadd + m * ldc) : (const float*)0;
    for (int c0 = wg * (TN / 2); c0 < (wg + 1) * (TN / 2); c0 += 32) {
      int n = n0 + c0;
      if (n >= N) break;
      uint32_t r[32];
      TCGEN05_LD_32X32B_X32(r, tmem + c0);
      TCGEN05_WAIT_LD();
      if (((ldc & 3) == 0) && (n + 32 <= N)) {
#pragma unroll
        for (int q = 0; q < 8; ++q) {
          float4 v;
          v.x = __uint_as_float(r[4 * q + 0]);
          v.y = __uint_as_float(r[4 * q + 1]);
          v.z = __uint_as_float(r[4 * q + 2]);
          v.w = __uint_as_float(r[4 * q + 3]);
          if (g.bias) {
            float4 bv = *(const float4*)(g.bias + n + 4 * q);
            v.x += bv.x; v.y += bv.y; v.z += bv.z; v.w += bv.w;
          }
          if (arow) {
            float4 av = *(const float4*)(arow + n + 4 * q);
            v.x += av.x; v.y += av.y; v.z += av.z; v.w += av.w;
          }
          *(float4*)(crow + n + 4 * q) = v;
        }
      } else {
        for (int j = 0; j < 32 && n + j < N; ++j) {
          float v = __uint_as_float(r[j]);
          if (g.bias) v += g.bias[n + j];
          if (arow) v += arow[n + j];
          crow[n + j] = v;
        }
      }
    }
    TCGEN05_FENCE_BEFORE();
  }
  __syncthreads();
  if (tid < 32) { TCGEN05_RELINQ(); TCGEN05_DEALLOC(tmem, TN); }
}

#else
// =====================================================================
// Naive fallback (sm_103 non-a pass; never selected at runtime)
// =====================================================================
template <int TN>
__global__ void __launch_bounds__(256) gemm3(GArg a0, GArg a1, size_t lda,
                                             size_t ldc, int N, int K) {
  const GArg g = blockIdx.z ? a1 : a0;
  int m0 = blockIdx.y * 128, n0 = blockIdx.x * TN;
  for (int e = threadIdx.x; e < 128 * TN; e += 256) {
    int m = m0 + e / TN, n = n0 + e % TN;
    if (n >= N) continue;
    float s = 0.f;
    const __nv_bfloat16 *ah = g.Ahi + (size_t)m * lda, *al = g.Alo + (size_t)m * lda;
    const __nv_bfloat16 *wh = g.Whi + (size_t)n * K, *wl = g.Wlo + (size_t)n * K;
    for (int k = 0; k < K; ++k)
      s += (__bfloat162float(ah[k]) + __bfloat162float(al[k])) *
           (__bfloat162float(wh[k]) + __bfloat162float(wl[k]));
    if (g.bias) s += g.bias[n];
    if (g.Cadd) s += g.Cadd[(size_t)m * ldc + n];
    g.C[(size_t)m * ldc + n] = s;
  }
}
#endif  // USE_TC

// ---------------- cvt_all ----------------
#define SEG0 16777216L
#define SEG1 (SEG0 + 1048576L)
#define SEG2 (SEG1 + 1048576L)
#define SEG3 (SEG2 + 262144L)
#define SEG4 (SEG3 + 524288L)
#define SEG5 (SEG4 + 1048576L)
#define SEG6 (SEG5 + 251904L)
#define SEG7 (SEG6 + 524288L)
#define SEG8 (SEG7 + 8192L)
__global__ void cvt_all(const float* __restrict__ dWhh, const float* __restrict__ eWf,
                        const float* __restrict__ eWb, const float* __restrict__ eOut,
                        const float* __restrict__ initW, const float* __restrict__ decWih,
                        const float* __restrict__ outW) {
  long idx = blockIdx.x * 256L + threadIdx.x;
  if (idx >= SEG8) return;
  if (idx < SEG0) {
    split_bf16(dWhh[idx], &g_dWhh_hi[idx], &g_dWhh_lo[idx]);
  } else if (idx < SEG1) {
    long i = idx - SEG0; split_bf16(eWf[i], &g_eWf_hi[i], &g_eWf_lo[i]);
  } else if (idx < SEG2) {
    long i = idx - SEG1; split_bf16(eWb[i], &g_eWb_hi[i], &g_eWb_lo[i]);
  } else if (idx < SEG3) {
    long i = idx - SEG2; split_bf16(eOut[i], &g_eOut_hi[i], &g_eOut_lo[i]);
  } else if (idx < SEG4) {
    long i = idx - SEG3; split_bf16(initW[i], &g_initW_hi[i], &g_initW_lo[i]);
  } else if (idx < SEG5) {
    long i = idx - SEG4;
    long n = i >> 7, k = i & 127;
    split_bf16(decWih[n * DLD + 5 + k], &g_zW_hi[i], &g_zW_lo[i]);
  } else if (idx < SEG6) {
    long i = idx - SEG5; split_bf16(outW[i], &g_outW_hi[i], &g_outW_lo[i]);
  } else if (idx < SEG7) {
    long i = idx - SEG6;
    g_hn_hi[i] = __float2bfloat16(0.0f);
    g_hn_lo[i] = __float2bfloat16(0.0f);
    g_ce[i] = 0.0f;
  } else {
    int r = (int)(idx - SEG7);
    g_dWih2[r] = make_float2(decWih[(long)r * DLD], decWih[(long)r * DLD + 1]);
  }
}

// ---------------- gate / small kernels ----------------
__global__ void enc_gate_kernel(const float* __restrict__ data,
                                const int* __restrict__ lengths,
                                const float* __restrict__ Wih_f,
                                const float* __restrict__ Wih_b, int t) {
  int idx = blockIdx.x * blockDim.x + threadIdx.x;
  int dir = idx >> 18;
  int rr = idx & ((1 << 18) - 1);
  int b = rr >> 9;
  int j = rr & 511;
  int L = lengths[b];
  L = L < 1 ? 1 : (L > NT ? NT : L);
  if (t >= L) return;
  int ti = dir ? (L - 1 - t) : t;
  float x0 = data[((size_t)b * DATALD + ti + 1) * 2 + 0];
  float x1 = data[((size_t)b * DATALD + ti + 1) * 2 + 1];
  const float* Wih = dir ? Wih_b : Wih_f;
  const float* G = g_Ge + (size_t)(dir * NB + b) * NGE;
  float pi = G[j]           + x0 * Wih[2 * j]               + x1 * Wih[2 * j + 1];
  float pf = G[NHE + j]     + x0 * Wih[2 * (NHE + j)]       + x1 * Wih[2 * (NHE + j) + 1];
  float pg = G[2 * NHE + j] + x0 * Wih[2 * (2 * NHE + j)]   + x1 * Wih[2 * (2 * NHE + j) + 1];
  float po = G[3 * NHE + j] + x0 * Wih[2 * (3 * NHE + j)]   + x1 * Wih[2 * (3 * NHE + j) + 1];
  int ci = (dir * NB + b) * NHE + j;
  float c = g_ce[ci];
  float c2 = sigf(pf) * c + sigf(pi) * tanhfast(pg);
  float h2 = sigf(po) * tanhfast(c2);
  g_ce[ci] = c2;
  int hidx = b * (2 * NHE) + dir * NHE + j;
  split_bf16(h2, &g_hn_hi[hidx], &g_hn_lo[hidx]);
}

__global__ void latent_kernel(const float* __restrict__ eps,
                              float* __restrict__ zm_out,
                              float* __restrict__ zl_out) {
  int idx = blockIdx.x * blockDim.x + threadIdx.x;
  int b = idx >> 7, k = idx & 127;
  float zm = g_zml[b * 256 + k];
  float zl = g_zml[b * 256 + 128 + k];
  zm_out[idx] = zm;
  zl_out[idx] = zl;
  float z = zm + expf(0.5f * zl) * eps[idx];
  split_bf16(z, &g_z_hi[idx], &g_z_lo[idx]);
}

__global__ void initsplit_kernel() {
  int idx = blockIdx.x * blockDim.x + threadIdx.x;
  int b = idx >> 11, j = idx & 2047;
  float h0 = tanhfast(g_init[b * (2 * NHD) + j]);
  float c0 = tanhfast(g_init[b * (2 * NHD) + NHD + j]);
  g_cd[idx] = c0;
  split_bf16(h0, &g_h0_hi[idx], &g_h0_lo[idx]);
}

__global__ void dec_gate_kernel(const float* __restrict__ data, int t) {
  int idx = blockIdx.x * blockDim.x + threadIdx.x;   // 512*1024 threads
  int b = idx >> 10, jp = (idx & 1023) << 1;
  float x0 = data[((size_t)b * DATALD + t) * 2 + 0];
  float x1 = data[((size_t)b * DATALD + t) * 2 + 1];
  const float* G = g_G + (size_t)b * NGD;
  float2 gi = *(const float2*)(G + jp);
  float2 gf = *(const float2*)(G + NHD + jp);
  float2 gg = *(const float2*)(G + 2 * NHD + jp);
  float2 go = *(const float2*)(G + 3 * NHD + jp);
  float4 wi = *(const float4*)(g_dWih2 + jp);
  float4 wf = *(const float4*)(g_dWih2 + NHD + jp);
  float4 wg = *(const float4*)(g_dWih2 + 2 * NHD + jp);
  float4 wo = *(const float4*)(g_dWih2 + 3 * NHD + jp);
  gi.x += x0 * wi.x + x1 * wi.y;  gi.y += x0 * wi.z + x1 * wi.w;
  gf.x += x0 * wf.x + x1 * wf.y;  gf.y += x0 * wf.z + x1 * wf.w;
  gg.x += x0 * wg.x + x1 * wg.y;  gg.y += x0 * wg.z + x1 * wg.w;
  go.x += x0 * wo.x + x1 * wo.y;  go.y += x0 * wo.z + x1 * wo.w;
  size_t cbase = (size_t)b * NHD + jp;
  float2 c = *(const float2*)(g_cd + cbase);
  float c20 = sigf(gf.x) * c.x + sigf(gi.x) * tanhfast(gg.x);
  float c21 = sigf(gf.y) * c.y + sigf(gi.y) * tanhfast(gg.y);
  float h20 = sigf(go.x) * tanhfast(c20);
  float h21 = sigf(go.y) * tanhfast(c21);
  *(float2*)(g_cd + cbase) = make_float2(c20, c21);
  size_t ho = ((size_t)b * NT + t) * NHD + jp;
  __nv_bfloat16 hh0, hl0, hh1, hl1;
  split_bf16(h20, &hh0, &hl0);
  split_bf16(h21, &hh1, &hl1);
  *(__nv_bfloat162*)(g_hs_hi + ho) = __nv_bfloat162(hh0, hh1);
  *(__nv_bfloat162*)(g_hs_lo + ho) = __nv_bfloat162(hl0, hl1);
}

// ---------------- launch ----------------
static inline void run_gemm(const GArg& a0, const GArg& a1, size_t lda, size_t ldc,
                            int N, int K, int M, int nz) {
  dim3 grid((unsigned)((N + 127) / 128), (unsigned)(M / 128), (unsigned)nz);
  gemm3<128><<<grid, 256, GS128>>>(a0, a1, lda, ldc, N, K);
}

extern "C" void kernel_launch(void* const* d_in, const int* in_sizes, int n_in,
                              void* d_out, int out_size) {
  const float* data      = (const float*)d_in[0];
  const float* eps       = (const float*)d_in[1];
  const float* enc_Wih_f = (const float*)d_in[2];
  const float* enc_Whh_f = (const float*)d_in[3];
  const float* enc_b_f   = (const float*)d_in[4];
  const float* enc_Wih_b = (const float*)d_in[5];
  const float* enc_Whh_b = (const float*)d_in[6];
  const float* enc_b_b   = (const float*)d_in[7];
  const float* enc_out_W = (const float*)d_in[8];
  const float* enc_out_b = (const float*)d_in[9];
  const float* init_W    = (const float*)d_in[10];
  const float* init_b    = (const float*)d_in[11];
  const float* dec_Wih   = (const float*)d_in[12];
  const float* dec_Whh   = (const float*)d_in[13];
  const float* dec_b     = (const float*)d_in[14];
  const float* out_W     = (const float*)d_in[15];
  const float* out_b     = (const float*)d_in[16];
  const int*   lengths   = (const int*)d_in[17];

  float* out    = (float*)d_out;
  float* params = out;
  float* zm_out = out + (size_t)NB * NT * NOUTD;
  float* zl_out = zm_out + (size_t)NB * NT;

  cudaFuncSetAttribute(gemm3<64>, cudaFuncAttributeMaxDynamicSharedMemorySize, GS64);
  cudaFuncSetAttribute(gemm3<128>, cudaFuncAttributeMaxDynamicSharedMemorySize, GS128);
  cudaFuncSetAttribute(gemm3<256>, cudaFuncAttributeMaxDynamicSharedMemorySize, GS);

#define SYM(p, s) cudaGetSymbolAddress((void**)&p, s)
  __nv_bfloat16 *dWhh_hi, *dWhh_lo, *eWf_hi, *eWf_lo, *eWb_hi, *eWb_lo;
  __nv_bfloat16 *eOut_hi, *eOut_lo, *initW_hi, *initW_lo, *zW_hi, *zW_lo, *outW_hi, *outW_lo;
  __nv_bfloat16 *hn_hi, *hn_lo, *z_hi, *z_lo, *h0_hi, *h0_lo, *hs_hi, *hs_lo;
  float *Ge, *zml, *initb, *zp, *G;
  SYM(dWhh_hi, g_dWhh_hi); SYM(dWhh_lo, g_dWhh_lo);
  SYM(eWf_hi, g_eWf_hi); SYM(eWf_lo, g_eWf_lo);
  SYM(eWb_hi, g_eWb_hi); SYM(eWb_lo, g_eWb_lo);
  SYM(eOut_hi, g_eOut_hi); SYM(eOut_lo, g_eOut_lo);
  SYM(initW_hi, g_initW_hi); SYM(initW_lo, g_initW_lo);
  SYM(zW_hi, g_zW_hi); SYM(zW_lo, g_zW_lo);
  SYM(outW_hi, g_outW_hi); SYM(outW_lo, g_outW_lo);
  SYM(hn_hi, g_hn_hi); SYM(hn_lo, g_hn_lo);
  SYM(z_hi, g_z_hi); SYM(z_lo, g_z_lo);
  SYM(h0_hi, g_h0_hi); SYM(h0_lo, g_h0_lo);
  SYM(hs_hi, g_hs_hi); SYM(hs_lo, g_hs_lo);
  SYM(Ge, g_Ge); SYM(zml, g_zml); SYM(initb, g_init); SYM(zp, g_zp); SYM(G, g_G);
#undef SYM

  cvt_all<<<(unsigned)((SEG8 + 255) / 256), 256>>>(
      dec_Whh, enc_Whh_f, enc_Whh_b, enc_out_W, init_W, dec_Wih, out_W);

  // ---- bidirectional encoder, 128 steps (TN=64 → 256 CTAs, 2/SM) ----
  for (int t = 0; t < NT; t++) {
    GArg f = {hn_hi, hn_lo, eWf_hi, eWf_lo, enc_b_f, nullptr, Ge};
    GArg bw = {hn_hi + NHE, hn_lo + NHE, eWb_hi, eWb_lo, enc_b_b, nullptr,
               Ge + (size_t)NB * NGE};
    gemm3<64><<<dim3(32, 4, 2), 256, GS64>>>(f, bw, 2 * NHE, NGE, NGE, NHE);
    enc_gate_kernel<<<2048, 256>>>(data, lengths, enc_Wih_f, enc_Wih_b, t);
  }

  // ---- latent ----
  {
    GArg a = {hn_hi, hn_lo, eOut_hi, eOut_lo, enc_out_b, nullptr, zml};
    run_gemm(a, a, 2 * NHE, 2 * NZ, 2 * NZ, 2 * NHE, NB, 1);
  }
  latent_kernel<<<256, 256>>>(eps, zm_out, zl_out);
  {
    GArg a = {z_hi, z_lo, initW_hi, initW_lo, init_b, nullptr, initb};
    run_gemm(a, a, NZ, 2 * NHD, 2 * NHD, NZ, NB, 1);
  }
  initsplit_kernel<<<4096, 256>>>();
  {
    GArg a = {z_hi, z_lo, zW_hi, zW_lo, dec_b, nullptr, zp};
    run_gemm(a, a, NZ, NGD, NGD, NZ, NB, 1);
  }

  // ---- decoder, 128 steps (gemm3<256> + gate) ----
  for (int t = 0; t < NT; t++) {
    const __nv_bfloat16* Ah = t ? (hs_hi + (size_t)(t - 1) * NHD) : h0_hi;
    const __nv_bfloat16* Al = t ? (hs_lo + (size_t)(t - 1) * NHD) : h0_lo;
    size_t lda = t ? (size_t)NT * NHD : (size_t)NHD;
    GArg a = {Ah, Al, dWhh_hi, dWhh_lo, nullptr, zp, G};
    gemm3<256><<<dim3(32, 4), 256, GS>>>(a, a, lda, NGD, NGD, NHD);
    dec_gate_kernel<<<2048, 256>>>(data, t);
  }

  // ---- output projection ----
  {
    GArg a = {hs_hi, hs_lo, outW_hi, outW_lo, out_b, nullptr, params};
    run_gemm(a, a, NHD, NOUTD, NOUTD, NHD, NB * NT, 1);
  }
}

// round 13
// speedup vs baseline: 1.0007x; 1.0007x over previous
#include <cuda_runtime.h>
#include <cuda_bf16.h>
#include <math.h>
#include <stdint.h>

#define NB 512
#define NT 128
#define NHE 512
#define NGE 2048
#define NZ 128
#define NHD 2048
#define NGD 8192
#define NOUTD 123
#define DATALD 129
#define DLD 133

#if !defined(__CUDA_ARCH__)
#define USE_TC 1
#elif defined(__CUDA_ARCH_FEAT_SM103_ALL) || defined(__CUDA_ARCH_FEAT_SM100_ALL)
#define USE_TC 1
#else
#define USE_TC 0
#endif

// ---------------- device scratch ----------------
__device__ __nv_bfloat16 g_dWhh_hi[NGD * NHD];
__device__ __nv_bfloat16 g_dWhh_lo[NGD * NHD];
__device__ __nv_bfloat16 g_eWf_hi[NGE * NHE];
__device__ __nv_bfloat16 g_eWf_lo[NGE * NHE];
__device__ __nv_bfloat16 g_eWb_hi[NGE * NHE];
__device__ __nv_bfloat16 g_eWb_lo[NGE * NHE];
__device__ __nv_bfloat16 g_eOut_hi[2 * NZ * 2 * NHE];
__device__ __nv_bfloat16 g_eOut_lo[2 * NZ * 2 * NHE];
__device__ __nv_bfloat16 g_initW_hi[2 * NHD * NZ];
__device__ __nv_bfloat16 g_initW_lo[2 * NHD * NZ];
__device__ __nv_bfloat16 g_zW_hi[NGD * NZ];
__device__ __nv_bfloat16 g_zW_lo[NGD * NZ];
__device__ __nv_bfloat16 g_outW_hi[NOUTD * NHD];
__device__ __nv_bfloat16 g_outW_lo[NOUTD * NHD];
__device__ float2 g_dWih2[NGD];

__device__ __nv_bfloat16 g_hn_hi[NB * 2 * NHE];
__device__ __nv_bfloat16 g_hn_lo[NB * 2 * NHE];
__device__ float g_ce[2 * NB * NHE];
__device__ float g_Ge[2 * NB * NGE];
__device__ float g_zml[NB * 2 * NZ];
__device__ __nv_bfloat16 g_z_hi[NB * NZ];
__device__ __nv_bfloat16 g_z_lo[NB * NZ];
__device__ float g_init[NB * 2 * NHD];
__device__ __nv_bfloat16 g_h0_hi[NB * NHD];
__device__ __nv_bfloat16 g_h0_lo[NB * NHD];
__device__ float g_cd[NB * NHD];
__device__ float g_zp[NB * NGD];
__device__ float g_G[NB * NGD];
__device__ __nv_bfloat16 g_hs_hi[(size_t)NB * NT * NHD];
__device__ __nv_bfloat16 g_hs_lo[(size_t)NB * NT * NHD];

// ---------------- helpers ----------------
__device__ __forceinline__ uint32_t smem_u32(const void* p) {
  uint32_t a;
  asm("{ .reg .u64 t; cvta.to.shared.u64 t, %1; cvt.u32.u64 %0, t; }" : "=r"(a) : "l"(p));
  return a;
}
__device__ __forceinline__ void cp16(uint32_t dst, const void* src, bool ok) {
  int sz = ok ? 16 : 0;
  asm volatile("cp.async.cg.shared.global [%0], [%1], 16, %2;\n"
               :: "r"(dst), "l"(src), "r"(sz) : "memory");
}
__device__ __forceinline__ void cp_commit() { asm volatile("cp.async.commit_group;" ::: "memory"); }
template <int N>
__device__ __forceinline__ void cp_wait() { asm volatile("cp.async.wait_group %0;" :: "n"(N) : "memory"); }

__device__ __forceinline__ float sigf(float x) {
  return __fdividef(1.0f, 1.0f + __expf(-x));
}
__device__ __forceinline__ float tanhfast(float x) {
  return 2.0f * sigf(2.0f * x) - 1.0f;
}
__device__ __forceinline__ void split_bf16(float x, __nv_bfloat16* hi, __nv_bfloat16* lo) {
  __nv_bfloat16 h = __float2bfloat16(x);
  *hi = h;
  *lo = __float2bfloat16(x - __bfloat162float(h));
}

struct GArg {
  const __nv_bfloat16 *Ahi, *Alo;  // [M][K] stride lda
  const __nv_bfloat16 *Whi, *Wlo;  // [N][K] packed
  const float *bias;
  const float *Cadd;
  float *C;
};

#define GS 197632u    // TN=256/S=4 and TN=128/S=6 both = 1024 + 196608

#if USE_TC
// =====================================================================
// tcgen05 path — KC=32/SW64 S-stage pipelined GEMM, lookahead LOOK
// =====================================================================
__device__ __forceinline__ uint32_t elect_one_pred() {
  uint32_t pred;
  asm volatile(
      "{\n\t.reg .pred p;\n\telect.sync _|p, 0xFFFFFFFF;\n\tselp.b32 %0, 1, 0, p;\n\t}"
      : "=r"(pred));
  return pred;
}
#define MBARRIER_INIT(addr, cnt) \
  asm volatile("mbarrier.init.shared.b64 [%0], %1;" :: "r"((uint32_t)(addr)), "r"((uint32_t)(cnt)) : "memory")
#define MBARRIER_WAIT_PARITY(addr, par) do {                                        \
  uint32_t _m = (uint32_t)(addr); uint32_t _p = (uint32_t)(par);                    \
  asm volatile("{\n\t.reg .pred P1;\n\t"                                            \
    "WL_%=:\n\t"                                                                    \
    "mbarrier.try_wait.parity.acquire.cta.shared::cta.b64 P1, [%0], %1, 0x989680;\n\t" \
    "@P1 bra.uni WD_%=;\n\t"                                                        \
    "bra.uni WL_%=;\n\t"                                                            \
    "WD_%=:\n\t}" :: "r"(_m), "r"(_p) : "memory");                                  \
} while (0)

#define TCGEN05_ALLOC(sm, n) \
  asm volatile("tcgen05.alloc.cta_group::1.sync.aligned.shared::cta.b32 [%0], %1;" \
               :: "r"((uint32_t)(sm)), "r"((uint32_t)(n)) : "memory")
#define TCGEN05_DEALLOC(t, n) \
  asm volatile("tcgen05.dealloc.cta_group::1.sync.aligned.b32 %0, %1;" :: "r"(t), "r"((uint32_t)(n)))
#define TCGEN05_RELINQ() \
  asm volatile("tcgen05.relinquish_alloc_permit.cta_group::1.sync.aligned;")
#define TCGEN05_COMMIT(mb) \
  asm volatile("tcgen05.commit.cta_group::1.mbarrier::arrive::one.shared::cluster.b64 [%0];" \
               :: "r"((uint32_t)(mb)) : "memory")
#define TCGEN05_FENCE_AFTER()  asm volatile("tcgen05.fence::after_thread_sync;" ::: "memory")
#define TCGEN05_FENCE_BEFORE() asm volatile("tcgen05.fence::before_thread_sync;" ::: "memory")
#define TCGEN05_WAIT_LD()      asm volatile("tcgen05.wait::ld.sync.aligned;" ::: "memory")
#define TCGEN05_LD_32X32B_X32(r, addr)                                            \
  asm volatile(                                                                   \
      "tcgen05.ld.sync.aligned.32x32b.x32.b32 "                                   \
      "{%0, %1, %2, %3, %4, %5, %6, %7, %8, %9, %10, %11, %12, %13, %14, %15, "   \
      " %16, %17, %18, %19, %20, %21, %22, %23, %24, %25, %26, %27, %28, %29, %30, %31}, [%32];" \
      : "=r"((r)[0]), "=r"((r)[1]), "=r"((r)[2]), "=r"((r)[3]),                   \
        "=r"((r)[4]), "=r"((r)[5]), "=r"((r)[6]), "=r"((r)[7]),                   \
        "=r"((r)[8]), "=r"((r)[9]), "=r"((r)[10]), "=r"((r)[11]),                 \
        "=r"((r)[12]), "=r"((r)[13]), "=r"((r)[14]), "=r"((r)[15]),               \
        "=r"((r)[16]), "=r"((r)[17]), "=r"((r)[18]), "=r"((r)[19]),               \
        "=r"((r)[20]), "=r"((r)[21]), "=r"((r)[22]), "=r"((r)[23]),               \
        "=r"((r)[24]), "=r"((r)[25]), "=r"((r)[26]), "=r"((r)[27]),               \
        "=r"((r)[28]), "=r"((r)[29]), "=r"((r)[30]), "=r"((r)[31])                \
      : "r"(addr))

static constexpr unsigned long long SMEM_DESC_BASE_SW64 =
    (4ull << 61) | (1ull << 46) | (32ull << 32) | (1ull << 16);
#define MAKE_SMEM_DESC64(a) (SMEM_DESC_BASE_SW64 | ((unsigned long long)((a) >> 4) & 0x3FFF))

template <int TN>
__device__ __forceinline__ void mma_cg1(uint32_t d, unsigned long long a,
                                        unsigned long long b, uint32_t en) {
  constexpr uint32_t idesc =
      (1u << 4) | (1u << 7) | (1u << 10) | ((TN / 8u) << 17) | (8u << 24);
  asm volatile(
      "{\n\t.reg .pred p;\n\tsetp.ne.u32 p, %4, 0;\n\t"
      "tcgen05.mma.cta_group::1.kind::f16 [%0], %1, %2, %3, {%5, %5, %5, %5}, p;\n\t}"
      :: "r"(d), "l"(a), "l"(b), "r"(idesc), "r"(en), "r"(0u) : "memory");
}

// KC=32/SW64 stage: Ahi@0(8K), Alo@8K, Bhi@16K(TN*64), Blo after
template <int TN>
__device__ __forceinline__ void load_stageP(
    uint32_t sbase, int stage, int ci, const GArg& g,
    size_t lda, int m0, int n0, int N, int K, int tid)
{
  const uint32_t stb = 16384u + (uint32_t)TN * 128u;
  const uint32_t base = sbase + (uint32_t)stage * stb;
  const int k0 = ci << 5;
#pragma unroll
  for (int it = 0; it < 2; ++it) {   // A: 128 rows x 4 chunks = 512
    int idx = tid + (it << 8);
    int row = idx >> 2, c = idx & 3;
    uint32_t off = (uint32_t)((row << 6) + (c << 4));
    off ^= ((off >> 3) & 0x30);
    size_t so = (size_t)(m0 + row) * lda + (size_t)k0 + (c << 3);
    cp16(base + off, g.Ahi + so, true);
    cp16(base + 8192u + off, g.Alo + so, true);
  }
#pragma unroll
  for (int it = 0; it < TN / 64; ++it) {  // B: TN rows x 4 chunks
    int idx = tid + (it << 8);
    int row = idx >> 2, c = idx & 3;
    int n = n0 + row;
    bool ok = (n < N);
    uint32_t off = (uint32_t)((row << 6) + (c << 4));
    off ^= ((off >> 3) & 0x30);
    size_t so = (size_t)(ok ? n : 0) * (size_t)K + (size_t)k0 + (c << 3);
    cp16(base + 16384u + off, g.Whi + so, ok);
    cp16(base + 16384u + (uint32_t)TN * 64u + off, g.Wlo + so, ok);
  }
  cp_commit();
}

template <int TN>
__device__ __forceinline__ void mma_chunkP(uint32_t sbase, int stage,
                                           uint32_t tmem, bool first) {
  const uint32_t stb = 16384u + (uint32_t)TN * 128u;
  uint32_t base = sbase + (uint32_t)stage * stb;
  unsigned long long dAh = MAKE_SMEM_DESC64(base);
  unsigned long long dAl = MAKE_SMEM_DESC64(base + 8192u);
  unsigned long long dBh = MAKE_SMEM_DESC64(base + 16384u);
  unsigned long long dBl = MAKE_SMEM_DESC64(base + 16384u + (uint32_t)TN * 64u);
#pragma unroll
  for (int ks = 0; ks < 2; ++ks) {
    unsigned long long o = (unsigned long long)(2 * ks);
    mma_cg1<TN>(tmem, dAh + o, dBh + o, (first && ks == 0) ? 0u : 1u);
    mma_cg1<TN>(tmem, dAh + o, dBl + o, 1u);
    mma_cg1<TN>(tmem, dAl + o, dBh + o, 1u);
  }
}

template <int TN, int S, int LOOK>
__global__ void __launch_bounds__(256) gemm3(GArg a0, GArg a1, size_t lda,
                                             size_t ldc, int N, int K) {
  extern __shared__ __align__(1024) char smem[];
  const int tid = threadIdx.x;
  const uint32_t sb = smem_u32(smem);
  const GArg g = blockIdx.z ? a1 : a0;
  const int m0 = blockIdx.y * 128;
  const int n0 = blockIdx.x * TN;
  const int nch = K >> 5;            // K multiple of 32, nch >= 4

  if (tid == 0)
    for (int s = 0; s < S; ++s) MBARRIER_INIT(sb + 16 + 8 * s, 1);
  if (tid < 32) TCGEN05_ALLOC(sb, TN);
  __syncthreads();
  uint32_t tmem;
  asm volatile("ld.shared.b32 %0, [%1];" : "=r"(tmem) : "r"(sb));

#pragma unroll
  for (int j = 0; j <= LOOK; ++j) {
    if (j < nch) load_stageP<TN>(sb + 1024u, j % S, j, g, lda, m0, n0, N, K, tid);
    else cp_commit();
  }

  for (int i = 0; i < nch; ++i) {
    const int s = i % S;
    if (i >= 1) {                    // delayed issue: load chunk i+LOOK
      int nc = i + LOOK;
      if (nc < nch) {
        if (nc >= S) MBARRIER_WAIT_PARITY(sb + 16 + 8 * (nc % S), ((nc - S) / S) & 1);
        load_stageP<TN>(sb + 1024u, nc % S, nc, g, lda, m0, n0, N, K, tid);
      } else cp_commit();
    }
    cp_wait<LOOK>();
    asm volatile("fence.proxy.async.shared::cta;" ::: "memory");
    __syncthreads();
    if (tid < 32 && elect_one_pred()) {
      mma_chunkP<TN>(sb + 1024u, s, tmem, i == 0);
      TCGEN05_COMMIT(sb + 16 + 8 * s);
    }
  }
  MBARRIER_WAIT_PARITY(sb + 16 + 8 * ((nch - 1) % S), ((nch - 1) / S) & 1);
  TCGEN05_FENCE_AFTER();

  {
    const int wq = (tid >> 5) & 3, wg = tid >> 7, lane = tid & 31;
    const size_t m = (size_t)m0 + (size_t)(wq * 32 + lane);
    float* crow = g.C + m * ldc;
    const float* arow = g.Cadd ? (g.Cadd + m * ldc) : (const float*)0;
    for (int c0 = wg * (TN / 2); c0 < (wg + 1) * (TN / 2); c0 += 32) {
      int n = n0 + c0;
      if (n >= N) break;
      uint32_t r[32];
      TCGEN05_LD_32X32B_X32(r, tmem + c0);
      TCGEN05_WAIT_LD();
      if (((ldc & 3) == 0) && (n + 32 <= N)) {
#pragma unroll
        for (int q = 0; q < 8; ++q) {
          float4 v;
          v.x = __uint_as_float(r[4 * q + 0]);
          v.y = __uint_as_float(r[4 * q + 1]);
          v.z = __uint_as_float(r[4 * q + 2]);
          v.w = __uint_as_float(r[4 * q + 3]);
          if (g.bias) {
            float4 bv = *(const float4*)(g.bias + n + 4 * q);
            v.x += bv.x; v.y += bv.y; v.z += bv.z; v.w += bv.w;
          }
          if (arow) {
            float4 av = *(const float4*)(arow + n + 4 * q);
            v.x += av.x; v.y += av.y; v.z += av.z; v.w += av.w;
          }
          *(float4*)(crow + n + 4 * q) = v;
        }
      } else {
        for (int j = 0; j < 32 && n + j < N; ++j) {
          float v = __uint_as_float(r[j]);
          if (g.bias) v += g.bias[n + j];
          if (arow) v += arow[n + j];
          crow[n + j] = v;
        }
      }
    }
    TCGEN05_FENCE_BEFORE();
  }
  __syncthreads();
  if (tid < 32) { TCGEN05_RELINQ(); TCGEN05_DEALLOC(tmem, TN); }
}

#else
// =====================================================================
// Naive fallback (sm_103 non-a pass; never selected at runtime)
// =====================================================================
template <int TN, int S, int LOOK>
__global__ void __launch_bounds__(256) gemm3(GArg a0, GArg a1, size_t lda,
                                             size_t ldc, int N, int K) {
  const GArg g = blockIdx.z ? a1 : a0;
  int m0 = blockIdx.y * 128, n0 = blockIdx.x * TN;
  for (int e = threadIdx.x; e < 128 * TN; e += 256) {
    int m = m0 + e / TN, n = n0 + e % TN;
    if (n >= N) continue;
    float s = 0.f;
    const __nv_bfloat16 *ah = g.Ahi + (size_t)m * lda, *al = g.Alo + (size_t)m * lda;
    const __nv_bfloat16 *wh = g.Whi + (size_t)n * K, *wl = g.Wlo + (size_t)n * K;
    for (int k = 0; k < K; ++k)
      s += (__bfloat162float(ah[k]) + __bfloat162float(al[k])) *
           (__bfloat162float(wh[k]) + __bfloat162float(wl[k]));
    if (g.bias) s += g.bias[n];
    if (g.Cadd) s += g.Cadd[(size_t)m * ldc + n];
    g.C[(size_t)m * ldc + n] = s;
  }
}
#endif  // USE_TC

// ---------------- cvt_all ----------------
#define SEG0 16777216L
#define SEG1 (SEG0 + 1048576L)
#define SEG2 (SEG1 + 1048576L)
#define SEG3 (SEG2 + 262144L)
#define SEG4 (SEG3 + 524288L)
#define SEG5 (SEG4 + 1048576L)
#define SEG6 (SEG5 + 251904L)
#define SEG7 (SEG6 + 524288L)
#define SEG8 (SEG7 + 8192L)
__global__ void cvt_all(const float* __restrict__ dWhh, const float* __restrict__ eWf,
                        const float* __restrict__ eWb, const float* __restrict__ eOut,
                        const float* __restrict__ initW, const float* __restrict__ decWih,
                        const float* __restrict__ outW) {
  long idx = blockIdx.x * 256L + threadIdx.x;
  if (idx >= SEG8) return;
  if (idx < SEG0) {
    split_bf16(dWhh[idx], &g_dWhh_hi[idx], &g_dWhh_lo[idx]);
  } else if (idx < SEG1) {
    long i = idx - SEG0; split_bf16(eWf[i], &g_eWf_hi[i], &g_eWf_lo[i]);
  } else if (idx < SEG2) {
    long i = idx - SEG1; split_bf16(eWb[i], &g_eWb_hi[i], &g_eWb_lo[i]);
  } else if (idx < SEG3) {
    long i = idx - SEG2; split_bf16(eOut[i], &g_eOut_hi[i], &g_eOut_lo[i]);
  } else if (idx < SEG4) {
    long i = idx - SEG3; split_bf16(initW[i], &g_initW_hi[i], &g_initW_lo[i]);
  } else if (idx < SEG5) {
    long i = idx - SEG4;
    long n = i >> 7, k = i & 127;
    split_bf16(decWih[n * DLD + 5 + k], &g_zW_hi[i], &g_zW_lo[i]);
  } else if (idx < SEG6) {
    long i = idx - SEG5; split_bf16(outW[i], &g_outW_hi[i], &g_outW_lo[i]);
  } else if (idx < SEG7) {
    long i = idx - SEG6;
    g_hn_hi[i] = __float2bfloat16(0.0f);
    g_hn_lo[i] = __float2bfloat16(0.0f);
    g_ce[i] = 0.0f;
  } else {
    int r = (int)(idx - SEG7);
    g_dWih2[r] = make_float2(decWih[(long)r * DLD], decWih[(long)r * DLD + 1]);
  }
}

// ---------------- gate / small kernels ----------------
__global__ void enc_gate_kernel(const float* __restrict__ data,
                                const int* __restrict__ lengths,
                                const float* __restrict__ Wih_f,
                                const float* __restrict__ Wih_b, int t) {
  int idx = blockIdx.x * blockDim.x + threadIdx.x;
  int dir = idx >> 18;
  int rr = idx & ((1 << 18) - 1);
  int b = rr >> 9;
  int j = rr & 511;
  int L = lengths[b];
  L = L < 1 ? 1 : (L > NT ? NT : L);
  if (t >= L) return;
  int ti = dir ? (L - 1 - t) : t;
  float x0 = data[((size_t)b * DATALD + ti + 1) * 2 + 0];
  float x1 = data[((size_t)b * DATALD + ti + 1) * 2 + 1];
  const float* Wih = dir ? Wih_b : Wih_f;
  const float* G = g_Ge + (size_t)(dir * NB + b) * NGE;
  float pi = G[j]           + x0 * Wih[2 * j]               + x1 * Wih[2 * j + 1];
  float pf = G[NHE + j]     + x0 * Wih[2 * (NHE + j)]       + x1 * Wih[2 * (NHE + j) + 1];
  float pg = G[2 * NHE + j] + x0 * Wih[2 * (2 * NHE + j)]   + x1 * Wih[2 * (2 * NHE + j) + 1];
  float po = G[3 * NHE + j] + x0 * Wih[2 * (3 * NHE + j)]   + x1 * Wih[2 * (3 * NHE + j) + 1];
  int ci = (dir * NB + b) * NHE + j;
  float c = g_ce[ci];
  float c2 = sigf(pf) * c + sigf(pi) * tanhfast(pg);
  float h2 = sigf(po) * tanhfast(c2);
  g_ce[ci] = c2;
  int hidx = b * (2 * NHE) + dir * NHE + j;
  split_bf16(h2, &g_hn_hi[hidx], &g_hn_lo[hidx]);
}

__global__ void latent_kernel(const float* __restrict__ eps,
                              float* __restrict__ zm_out,
                              float* __restrict__ zl_out) {
  int idx = blockIdx.x * blockDim.x + threadIdx.x;
  int b = idx >> 7, k = idx & 127;
  float zm = g_zml[b * 256 + k];
  float zl = g_zml[b * 256 + 128 + k];
  zm_out[idx] = zm;
  zl_out[idx] = zl;
  float z = zm + expf(0.5f * zl) * eps[idx];
  split_bf16(z, &g_z_hi[idx], &g_z_lo[idx]);
}

__global__ void initsplit_kernel() {
  int idx = blockIdx.x * blockDim.x + threadIdx.x;
  int b = idx >> 11, j = idx & 2047;
  float h0 = tanhfast(g_init[b * (2 * NHD) + j]);
  float c0 = tanhfast(g_init[b * (2 * NHD) + NHD + j]);
  g_cd[idx] = c0;
  split_bf16(h0, &g_h0_hi[idx], &g_h0_lo[idx]);
}

__global__ void dec_gate_kernel(const float* __restrict__ data, int t) {
  int idx = blockIdx.x * blockDim.x + threadIdx.x;   // 512*1024 threads
  int b = idx >> 10, jp = (idx & 1023) << 1;
  float x0 = data[((size_t)b * DATALD + t) * 2 + 0];
  float x1 = data[((size_t)b * DATALD + t) * 2 + 1];
  const float* G = g_G + (size_t)b * NGD;
  float2 gi = *(const float2*)(G + jp);
  float2 gf = *(const float2*)(G + NHD + jp);
  float2 gg = *(const float2*)(G + 2 * NHD + jp);
  float2 go = *(const float2*)(G + 3 * NHD + jp);
  float4 wi = *(const float4*)(g_dWih2 + jp);
  float4 wf = *(const float4*)(g_dWih2 + NHD + jp);
  float4 wg = *(const float4*)(g_dWih2 + 2 * NHD + jp);
  float4 wo = *(const float4*)(g_dWih2 + 3 * NHD + jp);
  gi.x += x0 * wi.x + x1 * wi.y;  gi.y += x0 * wi.z + x1 * wi.w;
  gf.x += x0 * wf.x + x1 * wf.y;  gf.y += x0 * wf.z + x1 * wf.w;
  gg.x += x0 * wg.x + x1 * wg.y;  gg.y += x0 * wg.z + x1 * wg.w;
  go.x += x0 * wo.x + x1 * wo.y;  go.y += x0 * wo.z + x1 * wo.w;
  size_t cbase = (size_t)b * NHD + jp;
  float2 c = *(const float2*)(g_cd + cbase);
  float c20 = sigf(gf.x) * c.x + sigf(gi.x) * tanhfast(gg.x);
  float c21 = sigf(gf.y) * c.y + sigf(gi.y) * tanhfast(gg.y);
  float h20 = sigf(go.x) * tanhfast(c20);
  float h21 = sigf(go.y) * tanhfast(c21);
  *(float2*)(g_cd + cbase) = make_float2(c20, c21);
  size_t ho = ((size_t)b * NT + t) * NHD + jp;
  __nv_bfloat16 hh0, hl0, hh1, hl1;
  split_bf16(h20, &hh0, &hl0);
  split_bf16(h21, &hh1, &hl1);
  *(__nv_bfloat162*)(g_hs_hi + ho) = __nv_bfloat162(hh0, hh1);
  *(__nv_bfloat162*)(g_hs_lo + ho) = __nv_bfloat162(hl0, hl1);
}

// ---------------- launch ----------------
static inline void run_gemm(const GArg& a0, const GArg& a1, size_t lda, size_t ldc,
                            int N, int K, int M, int nz) {
  dim3 grid((unsigned)((N + 127) / 128), (unsigned)(M / 128), (unsigned)nz);
  gemm3<128, 6, 4><<<grid, 256, GS>>>(a0, a1, lda, ldc, N, K);
}

extern "C" void kernel_launch(void* const* d_in, const int* in_sizes, int n_in,
                              void* d_out, int out_size) {
  const float* data      = (const float*)d_in[0];
  const float* eps       = (const float*)d_in[1];
  const float* enc_Wih_f = (const float*)d_in[2];
  const float* enc_Whh_f = (const float*)d_in[3];
  const float* enc_b_f   = (const float*)d_in[4];
  const float* enc_Wih_b = (const float*)d_in[5];
  const float* enc_Whh_b = (const float*)d_in[6];
  const float* enc_b_b   = (const float*)d_in[7];
  const float* enc_out_W = (const float*)d_in[8];
  const float* enc_out_b = (const float*)d_in[9];
  const float* init_W    = (const float*)d_in[10];
  const float* init_b    = (const float*)d_in[11];
  const float* dec_Wih   = (const float*)d_in[12];
  const float* dec_Whh   = (const float*)d_in[13];
  const float* dec_b     = (const float*)d_in[14];
  const float* out_W     = (const float*)d_in[15];
  const float* out_b     = (const float*)d_in[16];
  const int*   lengths   = (const int*)d_in[17];

  float* out    = (float*)d_out;
  float* params = out;
  float* zm_out = out + (size_t)NB * NT * NOUTD;
  float* zl_out = zm_out + (size_t)NB * NT;

  cudaFuncSetAttribute(gemm3<128, 6, 4>, cudaFuncAttributeMaxDynamicSharedMemorySize, GS);
  cudaFuncSetAttribute(gemm3<256, 4, 2>, cudaFuncAttributeMaxDynamicSharedMemorySize, GS);

#define SYM(p, s) cudaGetSymbolAddress((void**)&p, s)
  __nv_bfloat16 *dWhh_hi, *dWhh_lo, *eWf_hi, *eWf_lo, *eWb_hi, *eWb_lo;
  __nv_bfloat16 *eOut_hi, *eOut_lo, *initW_hi, *initW_lo, *zW_hi, *zW_lo, *outW_hi, *outW_lo;
  __nv_bfloat16 *hn_hi, *hn_lo, *z_hi, *z_lo, *h0_hi, *h0_lo, *hs_hi, *hs_lo;
  float *Ge, *zml, *initb, *zp, *G;
  SYM(dWhh_hi, g_dWhh_hi); SYM(dWhh_lo, g_dWhh_lo);
  SYM(eWf_hi, g_eWf_hi); SYM(eWf_lo, g_eWf_lo);
  SYM(eWb_hi, g_eWb_hi); SYM(eWb_lo, g_eWb_lo);
  SYM(eOut_hi, g_eOut_hi); SYM(eOut_lo, g_eOut_lo);
  SYM(initW_hi, g_initW_hi); SYM(initW_lo, g_initW_lo);
  SYM(zW_hi, g_zW_hi); SYM(zW_lo, g_zW_lo);
  SYM(outW_hi, g_outW_hi); SYM(outW_lo, g_outW_lo);
  SYM(hn_hi, g_hn_hi); SYM(hn_lo, g_hn_lo);
  SYM(z_hi, g_z_hi); SYM(z_lo, g_z_lo);
  SYM(h0_hi, g_h0_hi); SYM(h0_lo, g_h0_lo);
  SYM(hs_hi, g_hs_hi); SYM(hs_lo, g_hs_lo);
  SYM(Ge, g_Ge); SYM(zml, g_zml); SYM(initb, g_init); SYM(zp, g_zp); SYM(G, g_G);
#undef SYM

  cvt_all<<<(unsigned)((SEG8 + 255) / 256), 256>>>(
      dec_Whh, enc_Whh_f, enc_Whh_b, enc_out_W, init_W, dec_Wih, out_W);

  // ---- bidirectional encoder, 128 steps (TN=128, S=6, LOOK=4) ----
  for (int t = 0; t < NT; t++) {
    GArg f = {hn_hi, hn_lo, eWf_hi, eWf_lo, enc_b_f, nullptr, Ge};
    GArg bw = {hn_hi + NHE, hn_lo + NHE, eWb_hi, eWb_lo, enc_b_b, nullptr,
               Ge + (size_t)NB * NGE};
    run_gemm(f, bw, 2 * NHE, NGE, NGE, NHE, NB, 2);
    enc_gate_kernel<<<2048, 256>>>(data, lengths, enc_Wih_f, enc_Wih_b, t);
  }

  // ---- latent ----
  {
    GArg a = {hn_hi, hn_lo, eOut_hi, eOut_lo, enc_out_b, nullptr, zml};
    run_gemm(a, a, 2 * NHE, 2 * NZ, 2 * NZ, 2 * NHE, NB, 1);
  }
  latent_kernel<<<256, 256>>>(eps, zm_out, zl_out);
  {
    GArg a = {z_hi, z_lo, initW_hi, initW_lo, init_b, nullptr, initb};
    run_gemm(a, a, NZ, 2 * NHD, 2 * NHD, NZ, NB, 1);
  }
  initsplit_kernel<<<4096, 256>>>();
  {
    GArg a = {z_hi, z_lo, zW_hi, zW_lo, dec_b, nullptr, zp};
    run_gemm(a, a, NZ, NGD, NGD, NZ, NB, 1);
  }

  // ---- decoder, 128 steps (TN=256, S=4, LOOK=2 + gate) ----
  for (int t = 0; t < NT; t++) {
    const __nv_bfloat16* Ah = t ? (hs_hi + (size_t)(t - 1) * NHD) : h0_hi;
    const __nv_bfloat16* Al = t ? (hs_lo + (size_t)(t - 1) * NHD) : h0_lo;
    size_t lda = t ? (size_t)NT * NHD : (size_t)NHD;
    GArg a = {Ah, Al, dWhh_hi, dWhh_lo, nullptr, zp, G};
    gemm3<256, 4, 2><<<dim3(32, 4), 256, GS>>>(a, a, lda, NGD, NGD, NHD);
    dec_gate_kernel<<<2048, 256>>>(data, t);
  }

  // ---- output projection ----
  {
    GArg a = {hs_hi, hs_lo, outW_hi, outW_lo, out_b, nullptr, params};
    run_gemm(a, a, NHD, NOUTD, NOUTD, NHD, NB * NT, 1);
  }
}

// round 14
// speedup vs baseline: 1.0555x; 1.0548x over previous
#include <cuda_runtime.h>
#include <cuda_bf16.h>
#include <math.h>
#include <stdint.h>

#define NB 512
#define NT 128
#define NHE 512
#define NGE 2048
#define NZ 128
#define NHD 2048
#define NGD 8192
#define NOUTD 123
#define DATALD 129
#define DLD 133

#if !defined(__CUDA_ARCH__)
#define USE_TC 1
#elif defined(__CUDA_ARCH_FEAT_SM103_ALL) || defined(__CUDA_ARCH_FEAT_SM100_ALL)
#define USE_TC 1
#else
#define USE_TC 0
#endif

// ---------------- device scratch ----------------
__device__ __nv_bfloat16 g_dWhh_hi[NGD * NHD];
__device__ __nv_bfloat16 g_dWhh_lo[NGD * NHD];
__device__ __nv_bfloat16 g_eWf_hi[NGE * NHE];
__device__ __nv_bfloat16 g_eWf_lo[NGE * NHE];
__device__ __nv_bfloat16 g_eWb_hi[NGE * NHE];
__device__ __nv_bfloat16 g_eWb_lo[NGE * NHE];
__device__ __nv_bfloat16 g_eOut_hi[2 * NZ * 2 * NHE];
__device__ __nv_bfloat16 g_eOut_lo[2 * NZ * 2 * NHE];
__device__ __nv_bfloat16 g_initW_hi[2 * NHD * NZ];
__device__ __nv_bfloat16 g_initW_lo[2 * NHD * NZ];
__device__ __nv_bfloat16 g_zW_hi[NGD * NZ];
__device__ __nv_bfloat16 g_zW_lo[NGD * NZ];
__device__ __nv_bfloat16 g_outW_hi[NOUTD * NHD];
__device__ __nv_bfloat16 g_outW_lo[NOUTD * NHD];
__device__ float2 g_dWih2[NGD];

__device__ __nv_bfloat16 g_hn_hi[NB * 2 * NHE];
__device__ __nv_bfloat16 g_hn_lo[NB * 2 * NHE];
__device__ float g_ce[2 * NB * NHE];
__device__ float g_Ge[2 * NB * NGE];
__device__ float g_zml[NB * 2 * NZ];
__device__ __nv_bfloat16 g_z_hi[NB * NZ];
__device__ __nv_bfloat16 g_z_lo[NB * NZ];
__device__ float g_init[NB * 2 * NHD];
__device__ __nv_bfloat16 g_h0_hi[NB * NHD];
__device__ __nv_bfloat16 g_h0_lo[NB * NHD];
__device__ float g_cd[NB * NHD];
__device__ float g_zp[NB * NGD];
__device__ float g_G[NB * NGD];
__device__ __nv_bfloat16 g_hs_hi[(size_t)NB * NT * NHD];
__device__ __nv_bfloat16 g_hs_lo[(size_t)NB * NT * NHD];

// ---------------- helpers ----------------
__device__ __forceinline__ uint32_t smem_u32(const void* p) {
  uint32_t a;
  asm("{ .reg .u64 t; cvta.to.shared.u64 t, %1; cvt.u32.u64 %0, t; }" : "=r"(a) : "l"(p));
  return a;
}
__device__ __forceinline__ void cp16(uint32_t dst, const void* src, bool ok) {
  int sz = ok ? 16 : 0;
  asm volatile("cp.async.cg.shared.global [%0], [%1], 16, %2;\n"
               :: "r"(dst), "l"(src), "r"(sz) : "memory");
}
__device__ __forceinline__ void cp_commit() { asm volatile("cp.async.commit_group;" ::: "memory"); }
template <int N>
__device__ __forceinline__ void cp_wait() { asm volatile("cp.async.wait_group %0;" :: "n"(N) : "memory"); }

__device__ __forceinline__ float sigf(float x) {
  return __fdividef(1.0f, 1.0f + __expf(-x));
}
__device__ __forceinline__ float tanhfast(float x) {
  return 2.0f * sigf(2.0f * x) - 1.0f;
}
__device__ __forceinline__ void split_bf16(float x, __nv_bfloat16* hi, __nv_bfloat16* lo) {
  __nv_bfloat16 h = __float2bfloat16(x);
  *hi = h;
  *lo = __float2bfloat16(x - __bfloat162float(h));
}

struct GArg {
  const __nv_bfloat16 *Ahi, *Alo;  // [M][K] stride lda
  const __nv_bfloat16 *Whi, *Wlo;  // [N][K] packed
  const float *bias;
  const float *Cadd;
  float *C;
};

#define GS 197632u           // TN=256/S=4: 1024 + 4*49152
#define GS128 132096u        // TN=128/S=4: 1024 + 4*32768

#if USE_TC
// =====================================================================
// tcgen05 path — KC=32/SW64 4-stage pipelined GEMM (R11 proven config)
// =====================================================================
__device__ __forceinline__ uint32_t elect_one_pred() {
  uint32_t pred;
  asm volatile(
      "{\n\t.reg .pred p;\n\telect.sync _|p, 0xFFFFFFFF;\n\tselp.b32 %0, 1, 0, p;\n\t}"
      : "=r"(pred));
  return pred;
}
#define MBARRIER_INIT(addr, cnt) \
  asm volatile("mbarrier.init.shared.b64 [%0], %1;" :: "r"((uint32_t)(addr)), "r"((uint32_t)(cnt)) : "memory")
#define MBARRIER_WAIT_PARITY(addr, par) do {                                        \
  uint32_t _m = (uint32_t)(addr); uint32_t _p = (uint32_t)(par);                    \
  asm volatile("{\n\t.reg .pred P1;\n\t"                                            \
    "WL_%=:\n\t"                                                                    \
    "mbarrier.try_wait.parity.acquire.cta.shared::cta.b64 P1, [%0], %1, 0x989680;\n\t" \
    "@P1 bra.uni WD_%=;\n\t"                                                        \
    "bra.uni WL_%=;\n\t"                                                            \
    "WD_%=:\n\t}" :: "r"(_m), "r"(_p) : "memory");                                  \
} while (0)

#define TCGEN05_ALLOC(sm, n) \
  asm volatile("tcgen05.alloc.cta_group::1.sync.aligned.shared::cta.b32 [%0], %1;" \
               :: "r"((uint32_t)(sm)), "r"((uint32_t)(n)) : "memory")
#define TCGEN05_DEALLOC(t, n) \
  asm volatile("tcgen05.dealloc.cta_group::1.sync.aligned.b32 %0, %1;" :: "r"(t), "r"((uint32_t)(n)))
#define TCGEN05_RELINQ() \
  asm volatile("tcgen05.relinquish_alloc_permit.cta_group::1.sync.aligned;")
#define TCGEN05_COMMIT(mb) \
  asm volatile("tcgen05.commit.cta_group::1.mbarrier::arrive::one.shared::cluster.b64 [%0];" \
               :: "r"((uint32_t)(mb)) : "memory")
#define TCGEN05_FENCE_AFTER()  asm volatile("tcgen05.fence::after_thread_sync;" ::: "memory")
#define TCGEN05_FENCE_BEFORE() asm volatile("tcgen05.fence::before_thread_sync;" ::: "memory")
#define TCGEN05_WAIT_LD()      asm volatile("tcgen05.wait::ld.sync.aligned;" ::: "memory")
#define TCGEN05_LD_32X32B_X32(r, addr)                                            \
  asm volatile(                                                                   \
      "tcgen05.ld.sync.aligned.32x32b.x32.b32 "                                   \
      "{%0, %1, %2, %3, %4, %5, %6, %7, %8, %9, %10, %11, %12, %13, %14, %15, "   \
      " %16, %17, %18, %19, %20, %21, %22, %23, %24, %25, %26, %27, %28, %29, %30, %31}, [%32];" \
      : "=r"((r)[0]), "=r"((r)[1]), "=r"((r)[2]), "=r"((r)[3]),                   \
        "=r"((r)[4]), "=r"((r)[5]), "=r"((r)[6]), "=r"((r)[7]),                   \
        "=r"((r)[8]), "=r"((r)[9]), "=r"((r)[10]), "=r"((r)[11]),                 \
        "=r"((r)[12]), "=r"((r)[13]), "=r"((r)[14]), "=r"((r)[15]),               \
        "=r"((r)[16]), "=r"((r)[17]), "=r"((r)[18]), "=r"((r)[19]),               \
        "=r"((r)[20]), "=r"((r)[21]), "=r"((r)[22]), "=r"((r)[23]),               \
        "=r"((r)[24]), "=r"((r)[25]), "=r"((r)[26]), "=r"((r)[27]),               \
        "=r"((r)[28]), "=r"((r)[29]), "=r"((r)[30]), "=r"((r)[31])                \
      : "r"(addr))

static constexpr unsigned long long SMEM_DESC_BASE_SW64 =
    (4ull << 61) | (1ull << 46) | (32ull << 32) | (1ull << 16);
#define MAKE_SMEM_DESC64(a) (SMEM_DESC_BASE_SW64 | ((unsigned long long)((a) >> 4) & 0x3FFF))

template <int TN>
__device__ __forceinline__ void mma_cg1(uint32_t d, unsigned long long a,
                                        unsigned long long b, uint32_t en) {
  constexpr uint32_t idesc =
      (1u << 4) | (1u << 7) | (1u << 10) | ((TN / 8u) << 17) | (8u << 24);
  asm volatile(
      "{\n\t.reg .pred p;\n\tsetp.ne.u32 p, %4, 0;\n\t"
      "tcgen05.mma.cta_group::1.kind::f16 [%0], %1, %2, %3, {%5, %5, %5, %5}, p;\n\t}"
      :: "r"(d), "l"(a), "l"(b), "r"(idesc), "r"(en), "r"(0u) : "memory");
}

// KC=32/SW64 stage: Ahi@0(8K), Alo@8K, Bhi@16K(TN*64), Blo after
template <int TN>
__device__ __forceinline__ void load_stageP(
    uint32_t sbase, int stage, int ci, const GArg& g,
    size_t lda, int m0, int n0, int N, int K, int tid)
{
  const uint32_t stb = 16384u + (uint32_t)TN * 128u;
  const uint32_t base = sbase + (uint32_t)stage * stb;
  const int k0 = ci << 5;
#pragma unroll
  for (int it = 0; it < 2; ++it) {   // A: 128 rows x 4 chunks = 512
    int idx = tid + (it << 8);
    int row = idx >> 2, c = idx & 3;
    uint32_t off = (uint32_t)((row << 6) + (c << 4));
    off ^= ((off >> 3) & 0x30);
    size_t so = (size_t)(m0 + row) * lda + (size_t)k0 + (c << 3);
    cp16(base + off, g.Ahi + so, true);
    cp16(base + 8192u + off, g.Alo + so, true);
  }
#pragma unroll
  for (int it = 0; it < TN / 64; ++it) {  // B: TN rows x 4 chunks
    int idx = tid + (it << 8);
    int row = idx >> 2, c = idx & 3;
    int n = n0 + row;
    bool ok = (n < N);
    uint32_t off = (uint32_t)((row << 6) + (c << 4));
    off ^= ((off >> 3) & 0x30);
    size_t so = (size_t)(ok ? n : 0) * (size_t)K + (size_t)k0 + (c << 3);
    cp16(base + 16384u + off, g.Whi + so, ok);
    cp16(base + 16384u + (uint32_t)TN * 64u + off, g.Wlo + so, ok);
  }
  cp_commit();
}

template <int TN>
__device__ __forceinline__ void mma_chunkP(uint32_t sbase, int stage,
                                           uint32_t tmem, bool first) {
  const uint32_t stb = 16384u + (uint32_t)TN * 128u;
  uint32_t base = sbase + (uint32_t)stage * stb;
  unsigned long long dAh = MAKE_SMEM_DESC64(base);
  unsigned long long dAl = MAKE_SMEM_DESC64(base + 8192u);
  unsigned long long dBh = MAKE_SMEM_DESC64(base + 16384u);
  unsigned long long dBl = MAKE_SMEM_DESC64(base + 16384u + (uint32_t)TN * 64u);
#pragma unroll
  for (int ks = 0; ks < 2; ++ks) {
    unsigned long long o = (unsigned long long)(2 * ks);
    mma_cg1<TN>(tmem, dAh + o, dBh + o, (first && ks == 0) ? 0u : 1u);
    mma_cg1<TN>(tmem, dAh + o, dBl + o, 1u);
    mma_cg1<TN>(tmem, dAl + o, dBh + o, 1u);
  }
}

// DSWZ: if true, grid is 1-D and m0/n0 derive from linear bid so the 4 CTAs
// sharing a B tile are adjacent (CLC contiguous placement → L2 locality).
template <int TN, bool DSWZ>
__global__ void __launch_bounds__(256) gemm3(GArg a0, GArg a1, size_t lda,
                                             size_t ldc, int N, int K) {
  extern __shared__ __align__(1024) char smem[];
  const int tid = threadIdx.x;
  const uint32_t sb = smem_u32(smem);
  const GArg g = blockIdx.z ? a1 : a0;
  int m0, n0;
  if (DSWZ) {
    m0 = ((int)blockIdx.x & 3) * 128;
    n0 = ((int)blockIdx.x >> 2) * TN;
  } else {
    m0 = blockIdx.y * 128;
    n0 = blockIdx.x * TN;
  }
  const int nch = K >> 5;            // K multiple of 32, nch >= 4

  if (tid == 0)
    for (int s = 0; s < 4; ++s) MBARRIER_INIT(sb + 16 + 8 * s, 1);
  if (tid < 32) TCGEN05_ALLOC(sb, TN);
  __syncthreads();
  uint32_t tmem;
  asm volatile("ld.shared.b32 %0, [%1];" : "=r"(tmem) : "r"(sb));

  load_stageP<TN>(sb + 1024u, 0, 0, g, lda, m0, n0, N, K, tid);
  load_stageP<TN>(sb + 1024u, 1, 1, g, lda, m0, n0, N, K, tid);
  load_stageP<TN>(sb + 1024u, 2, 2, g, lda, m0, n0, N, K, tid);

  for (int i = 0; i < nch; ++i) {
    const int s = i & 3;
    if (i >= 1) {                    // delayed issue: load chunk i+2
      int nc = i + 2;
      if (nc < nch) {
        if (nc >= 4) MBARRIER_WAIT_PARITY(sb + 16 + 8 * (nc & 3), ((nc - 4) >> 2) & 1);
        load_stageP<TN>(sb + 1024u, nc & 3, nc, g, lda, m0, n0, N, K, tid);
      } else cp_commit();
    }
    cp_wait<2>();
    asm volatile("fence.proxy.async.shared::cta;" ::: "memory");
    __syncthreads();
    if (tid < 32 && elect_one_pred()) {
      mma_chunkP<TN>(sb + 1024u, s, tmem, i == 0);
      TCGEN05_COMMIT(sb + 16 + 8 * s);
    }
  }
  MBARRIER_WAIT_PARITY(sb + 16 + 8 * ((nch - 1) & 3), ((nch - 1) >> 2) & 1);
  TCGEN05_FENCE_AFTER();

  {
    const int wq = (tid >> 5) & 3, wg = tid >> 7, lane = tid & 31;
    const size_t m = (size_t)m0 + (size_t)(wq * 32 + lane);
    float* crow = g.C + m * ldc;
    const float* arow = g.Cadd ? (g.Cadd + m * ldc) : (const float*)0;
    for (int c0 = wg * (TN / 2); c0 < (wg + 1) * (TN / 2); c0 += 32) {
      int n = n0 + c0;
      if (n >= N) break;
      uint32_t r[32];
      TCGEN05_LD_32X32B_X32(r, tmem + c0);
      TCGEN05_WAIT_LD();
      if (((ldc & 3) == 0) && (n + 32 <= N)) {
#pragma unroll
        for (int q = 0; q < 8; ++q) {
          float4 v;
          v.x = __uint_as_float(r[4 * q + 0]);
          v.y = __uint_as_float(r[4 * q + 1]);
          v.z = __uint_as_float(r[4 * q + 2]);
          v.w = __uint_as_float(r[4 * q + 3]);
          if (g.bias) {
            float4 bv = *(const float4*)(g.bias + n + 4 * q);
            v.x += bv.x; v.y += bv.y; v.z += bv.z; v.w += bv.w;
          }
          if (arow) {
            float4 av = *(const float4*)(arow + n + 4 * q);
            v.x += av.x; v.y += av.y; v.z += av.z; v.w += av.w;
          }
          *(float4*)(crow + n + 4 * q) = v;
        }
      } else {
        for (int j = 0; j < 32 && n + j < N; ++j) {
          float v = __uint_as_float(r[j]);
          if (g.bias) v += g.bias[n + j];
          if (arow) v += arow[n + j];
          crow[n + j] = v;
        }
      }
    }
    TCGEN05_FENCE_BEFORE();
  }
  __syncthreads();
  if (tid < 32) { TCGEN05_RELINQ(); TCGEN05_DEALLOC(tmem, TN); }
}

#else
// =====================================================================
// Naive fallback (sm_103 non-a pass; never selected at runtime)
// =====================================================================
template <int TN, bool DSWZ>
__global__ void __launch_bounds__(256) gemm3(GArg a0, GArg a1, size_t lda,
                                             size_t ldc, int N, int K) {
  const GArg g = blockIdx.z ? a1 : a0;
  int m0, n0;
  if (DSWZ) { m0 = ((int)blockIdx.x & 3) * 128; n0 = ((int)blockIdx.x >> 2) * TN; }
  else      { m0 = blockIdx.y * 128; n0 = blockIdx.x * TN; }
  for (int e = threadIdx.x; e < 128 * TN; e += 256) {
    int m = m0 + e / TN, n = n0 + e % TN;
    if (n >= N) continue;
    float s = 0.f;
    const __nv_bfloat16 *ah = g.Ahi + (size_t)m * lda, *al = g.Alo + (size_t)m * lda;
    const __nv_bfloat16 *wh = g.Whi + (size_t)n * K, *wl = g.Wlo + (size_t)n * K;
    for (int k = 0; k < K; ++k)
      s += (__bfloat162float(ah[k]) + __bfloat162float(al[k])) *
           (__bfloat162float(wh[k]) + __bfloat162float(wl[k]));
    if (g.bias) s += g.bias[n];
    if (g.Cadd) s += g.Cadd[(size_t)m * ldc + n];
    g.C[(size_t)m * ldc + n] = s;
  }
}
#endif  // USE_TC

// ---------------- cvt_all ----------------
#define SEG0 16777216L
#define SEG1 (SEG0 + 1048576L)
#define SEG2 (SEG1 + 1048576L)
#define SEG3 (SEG2 + 262144L)
#define SEG4 (SEG3 + 524288L)
#define SEG5 (SEG4 + 1048576L)
#define SEG6 (SEG5 + 251904L)
#define SEG7 (SEG6 + 524288L)
#define SEG8 (SEG7 + 8192L)
__global__ void cvt_all(const float* __restrict__ dWhh, const float* __restrict__ eWf,
                        const float* __restrict__ eWb, const float* __restrict__ eOut,
                        const float* __restrict__ initW, const float* __restrict__ decWih,
                        const float* __restrict__ outW) {
  long idx = blockIdx.x * 256L + threadIdx.x;
  if (idx >= SEG8) return;
  if (idx < SEG0) {
    split_bf16(dWhh[idx], &g_dWhh_hi[idx], &g_dWhh_lo[idx]);
  } else if (idx < SEG1) {
    long i = idx - SEG0; split_bf16(eWf[i], &g_eWf_hi[i], &g_eWf_lo[i]);
  } else if (idx < SEG2) {
    long i = idx - SEG1; split_bf16(eWb[i], &g_eWb_hi[i], &g_eWb_lo[i]);
  } else if (idx < SEG3) {
    long i = idx - SEG2; split_bf16(eOut[i], &g_eOut_hi[i], &g_eOut_lo[i]);
  } else if (idx < SEG4) {
    long i = idx - SEG3; split_bf16(initW[i], &g_initW_hi[i], &g_initW_lo[i]);
  } else if (idx < SEG5) {
    long i = idx - SEG4;
    long n = i >> 7, k = i & 127;
    split_bf16(decWih[n * DLD + 5 + k], &g_zW_hi[i], &g_zW_lo[i]);
  } else if (idx < SEG6) {
    long i = idx - SEG5; split_bf16(outW[i], &g_outW_hi[i], &g_outW_lo[i]);
  } else if (idx < SEG7) {
    long i = idx - SEG6;
    g_hn_hi[i] = __float2bfloat16(0.0f);
    g_hn_lo[i] = __float2bfloat16(0.0f);
    g_ce[i] = 0.0f;
  } else {
    int r = (int)(idx - SEG7);
    g_dWih2[r] = make_float2(decWih[(long)r * DLD], decWih[(long)r * DLD + 1]);
  }
}

// ---------------- gate / small kernels ----------------
__global__ void enc_gate_kernel(const float* __restrict__ data,
                                const int* __restrict__ lengths,
                                const float* __restrict__ Wih_f,
                                const float* __restrict__ Wih_b, int t) {
  int idx = blockIdx.x * blockDim.x + threadIdx.x;
  int dir = idx >> 18;
  int rr = idx & ((1 << 18) - 1);
  int b = rr >> 9;
  int j = rr & 511;
  int L = lengths[b];
  L = L < 1 ? 1 : (L > NT ? NT : L);
  if (t >= L) return;
  int ti = dir ? (L - 1 - t) : t;
  float x0 = data[((size_t)b * DATALD + ti + 1) * 2 + 0];
  float x1 = data[((size_t)b * DATALD + ti + 1) * 2 + 1];
  const float* Wih = dir ? Wih_b : Wih_f;
  const float* G = g_Ge + (size_t)(dir * NB + b) * NGE;
  float pi = G[j]           + x0 * Wih[2 * j]               + x1 * Wih[2 * j + 1];
  float pf = G[NHE + j]     + x0 * Wih[2 * (NHE + j)]       + x1 * Wih[2 * (NHE + j) + 1];
  float pg = G[2 * NHE + j] + x0 * Wih[2 * (2 * NHE + j)]   + x1 * Wih[2 * (2 * NHE + j) + 1];
  float po = G[3 * NHE + j] + x0 * Wih[2 * (3 * NHE + j)]   + x1 * Wih[2 * (3 * NHE + j) + 1];
  int ci = (dir * NB + b) * NHE + j;
  float c = g_ce[ci];
  float c2 = sigf(pf) * c + sigf(pi) * tanhfast(pg);
  float h2 = sigf(po) * tanhfast(c2);
  g_ce[ci] = c2;
  int hidx = b * (2 * NHE) + dir * NHE + j;
  split_bf16(h2, &g_hn_hi[hidx], &g_hn_lo[hidx]);
}

__global__ void latent_kernel(const float* __restrict__ eps,
                              float* __restrict__ zm_out,
                              float* __restrict__ zl_out) {
  int idx = blockIdx.x * blockDim.x + threadIdx.x;
  int b = idx >> 7, k = idx & 127;
  float zm = g_zml[b * 256 + k];
  float zl = g_zml[b * 256 + 128 + k];
  zm_out[idx] = zm;
  zl_out[idx] = zl;
  float z = zm + expf(0.5f * zl) * eps[idx];
  split_bf16(z, &g_z_hi[idx], &g_z_lo[idx]);
}

__global__ void initsplit_kernel() {
  int idx = blockIdx.x * blockDim.x + threadIdx.x;
  int b = idx >> 11, j = idx & 2047;
  float h0 = tanhfast(g_init[b * (2 * NHD) + j]);
  float c0 = tanhfast(g_init[b * (2 * NHD) + NHD + j]);
  g_cd[idx] = c0;
  split_bf16(h0, &g_h0_hi[idx], &g_h0_lo[idx]);
}

__global__ void dec_gate_kernel(const float* __restrict__ data, int t) {
  int idx = blockIdx.x * blockDim.x + threadIdx.x;   // 512*1024 threads
  int b = idx >> 10, jp = (idx & 1023) << 1;
  float x0 = data[((size_t)b * DATALD + t) * 2 + 0];
  float x1 = data[((size_t)b * DATALD + t) * 2 + 1];
  const float* G = g_G + (size_t)b * NGD;
  float2 gi = *(const float2*)(G + jp);
  float2 gf = *(const float2*)(G + NHD + jp);
  float2 gg = *(const float2*)(G + 2 * NHD + jp);
  float2 go = *(const float2*)(G + 3 * NHD + jp);
  float4 wi = *(const float4*)(g_dWih2 + jp);
  float4 wf = *(const float4*)(g_dWih2 + NHD + jp);
  float4 wg = *(const float4*)(g_dWih2 + 2 * NHD + jp);
  float4 wo = *(const float4*)(g_dWih2 + 3 * NHD + jp);
  gi.x += x0 * wi.x + x1 * wi.y;  gi.y += x0 * wi.z + x1 * wi.w;
  gf.x += x0 * wf.x + x1 * wf.y;  gf.y += x0 * wf.z + x1 * wf.w;
  gg.x += x0 * wg.x + x1 * wg.y;  gg.y += x0 * wg.z + x1 * wg.w;
  go.x += x0 * wo.x + x1 * wo.y;  go.y += x0 * wo.z + x1 * wo.w;
  size_t cbase = (size_t)b * NHD + jp;
  float2 c = *(const float2*)(g_cd + cbase);
  float c20 = sigf(gf.x) * c.x + sigf(gi.x) * tanhfast(gg.x);
  float c21 = sigf(gf.y) * c.y + sigf(gi.y) * tanhfast(gg.y);
  float h20 = sigf(go.x) * tanhfast(c20);
  float h21 = sigf(go.y) * tanhfast(c21);
  *(float2*)(g_cd + cbase) = make_float2(c20, c21);
  size_t ho = ((size_t)b * NT + t) * NHD + jp;
  __nv_bfloat16 hh0, hl0, hh1, hl1;
  split_bf16(h20, &hh0, &hl0);
  split_bf16(h21, &hh1, &hl1);
  *(__nv_bfloat162*)(g_hs_hi + ho) = __nv_bfloat162(hh0, hh1);
  *(__nv_bfloat162*)(g_hs_lo + ho) = __nv_bfloat162(hl0, hl1);
}

// ---------------- launch ----------------
static inline void run_gemm(const GArg& a0, const GArg& a1, size_t lda, size_t ldc,
                            int N, int K, int M, int nz) {
  dim3 grid((unsigned)((N + 127) / 128), (unsigned)(M / 128), (unsigned)nz);
  gemm3<128, false><<<grid, 256, GS128>>>(a0, a1, lda, ldc, N, K);
}

extern "C" void kernel_launch(void* const* d_in, const int* in_sizes, int n_in,
                              void* d_out, int out_size) {
  const float* data      = (const float*)d_in[0];
  const float* eps       = (const float*)d_in[1];
  const float* enc_Wih_f = (const float*)d_in[2];
  const float* enc_Whh_f = (const float*)d_in[3];
  const float* enc_b_f   = (const float*)d_in[4];
  const float* enc_Wih_b = (const float*)d_in[5];
  const float* enc_Whh_b = (const float*)d_in[6];
  const float* enc_b_b   = (const float*)d_in[7];
  const float* enc_out_W = (const float*)d_in[8];
  const float* enc_out_b = (const float*)d_in[9];
  const float* init_W    = (const float*)d_in[10];
  const float* init_b    = (const float*)d_in[11];
  const float* dec_Wih   = (const float*)d_in[12];
  const float* dec_Whh   = (const float*)d_in[13];
  const float* dec_b     = (const float*)d_in[14];
  const float* out_W     = (const float*)d_in[15];
  const float* out_b     = (const float*)d_in[16];
  const int*   lengths   = (const int*)d_in[17];

  float* out    = (float*)d_out;
  float* params = out;
  float* zm_out = out + (size_t)NB * NT * NOUTD;
  float* zl_out = zm_out + (size_t)NB * NT;

  cudaFuncSetAttribute(gemm3<128, false>, cudaFuncAttributeMaxDynamicSharedMemorySize, GS128);
  cudaFuncSetAttribute(gemm3<256, true>, cudaFuncAttributeMaxDynamicSharedMemorySize, GS);

#define SYM(p, s) cudaGetSymbolAddress((void**)&p, s)
  __nv_bfloat16 *dWhh_hi, *dWhh_lo, *eWf_hi, *eWf_lo, *eWb_hi, *eWb_lo;
  __nv_bfloat16 *eOut_hi, *eOut_lo, *initW_hi, *initW_lo, *zW_hi, *zW_lo, *outW_hi, *outW_lo;
  __nv_bfloat16 *hn_hi, *hn_lo, *z_hi, *z_lo, *h0_hi, *h0_lo, *hs_hi, *hs_lo;
  float *Ge, *zml, *initb, *zp, *G;
  SYM(dWhh_hi, g_dWhh_hi); SYM(dWhh_lo, g_dWhh_lo);
  SYM(eWf_hi, g_eWf_hi); SYM(eWf_lo, g_eWf_lo);
  SYM(eWb_hi, g_eWb_hi); SYM(eWb_lo, g_eWb_lo);
  SYM(eOut_hi, g_eOut_hi); SYM(eOut_lo, g_eOut_lo);
  SYM(initW_hi, g_initW_hi); SYM(initW_lo, g_initW_lo);
  SYM(zW_hi, g_zW_hi); SYM(zW_lo, g_zW_lo);
  SYM(outW_hi, g_outW_hi); SYM(outW_lo, g_outW_lo);
  SYM(hn_hi, g_hn_hi); SYM(hn_lo, g_hn_lo);
  SYM(z_hi, g_z_hi); SYM(z_lo, g_z_lo);
  SYM(h0_hi, g_h0_hi); SYM(h0_lo, g_h0_lo);
  SYM(hs_hi, g_hs_hi); SYM(hs_lo, g_hs_lo);
  SYM(Ge, g_Ge); SYM(zml, g_zml); SYM(initb, g_init); SYM(zp, g_zp); SYM(G, g_G);
#undef SYM

  cvt_all<<<(unsigned)((SEG8 + 255) / 256), 256>>>(
      dec_Whh, enc_Whh_f, enc_Whh_b, enc_out_W, init_W, dec_Wih, out_W);

  // ---- bidirectional encoder, 128 steps (TN=128, S=4, LOOK=2) ----
  for (int t = 0; t < NT; t++) {
    GArg f = {hn_hi, hn_lo, eWf_hi, eWf_lo, enc_b_f, nullptr, Ge};
    GArg bw = {hn_hi + NHE, hn_lo + NHE, eWb_hi, eWb_lo, enc_b_b, nullptr,
               Ge + (size_t)NB * NGE};
    run_gemm(f, bw, 2 * NHE, NGE, NGE, NHE, NB, 2);
    enc_gate_kernel<<<2048, 256>>>(data, lengths, enc_Wih_f, enc_Wih_b, t);
  }

  // ---- latent ----
  {
    GArg a = {hn_hi, hn_lo, eOut_hi, eOut_lo, enc_out_b, nullptr, zml};
    run_gemm(a, a, 2 * NHE, 2 * NZ, 2 * NZ, 2 * NHE, NB, 1);
  }
  latent_kernel<<<256, 256>>>(eps, zm_out, zl_out);
  {
    GArg a = {z_hi, z_lo, initW_hi, initW_lo, init_b, nullptr, initb};
    run_gemm(a, a, NZ, 2 * NHD, 2 * NHD, NZ, NB, 1);
  }
  initsplit_kernel<<<4096, 256>>>();
  {
    GArg a = {z_hi, z_lo, zW_hi, zW_lo, dec_b, nullptr, zp};
    run_gemm(a, a, NZ, NGD, NGD, NZ, NB, 1);
  }

  // ---- decoder, 128 steps (TN=256, 1-D swizzled grid + gate) ----
  for (int t = 0; t < NT; t++) {
    const __nv_bfloat16* Ah = t ? (hs_hi + (size_t)(t - 1) * NHD) : h0_hi;
    const __nv_bfloat16* Al = t ? (hs_lo + (size_t)(t - 1) * NHD) : h0_lo;
    size_t lda = t ? (size_t)NT * NHD : (size_t)NHD;
    GArg a = {Ah, Al, dWhh_hi, dWhh_lo, nullptr, zp, G};
    gemm3<256, true><<<128, 256, GS>>>(a, a, lda, NGD, NGD, NHD);
    dec_gate_kernel<<<2048, 256>>>(data, t);
  }

  // ---- output projection ----
  {
    GArg a = {hs_hi, hs_lo, outW_hi, outW_lo, out_b, nullptr, params};
    run_gemm(a, a, NHD, NOUTD, NOUTD, NHD, NB * NT, 1);
  }
}

// round 15
// speedup vs baseline: 1.1073x; 1.0491x over previous
#include <cuda_runtime.h>
#include <cuda_bf16.h>
#include <math.h>
#include <stdint.h>

#define NB 512
#define NT 128
#define NHE 512
#define NGE 2048
#define NZ 128
#define NHD 2048
#define NGD 8192
#define NOUTD 123
#define DATALD 129
#define DLD 133

#if !defined(__CUDA_ARCH__)
#define USE_TC 1
#elif defined(__CUDA_ARCH_FEAT_SM103_ALL) || defined(__CUDA_ARCH_FEAT_SM100_ALL)
#define USE_TC 1
#else
#define USE_TC 0
#endif

#if defined(__CUDA_ARCH__) && (__CUDA_ARCH__ >= 900)
#define GRID_SYNC() cudaGridDependencySynchronize()
#define GRID_TRIG() cudaTriggerProgrammaticLaunchCompletion()
#else
#define GRID_SYNC()
#define GRID_TRIG()
#endif

// ---------------- device scratch ----------------
__device__ __nv_bfloat16 g_dWhh_hi[NGD * NHD];
__device__ __nv_bfloat16 g_dWhh_lo[NGD * NHD];
__device__ __nv_bfloat16 g_eWf_hi[NGE * NHE];
__device__ __nv_bfloat16 g_eWf_lo[NGE * NHE];
__device__ __nv_bfloat16 g_eWb_hi[NGE * NHE];
__device__ __nv_bfloat16 g_eWb_lo[NGE * NHE];
__device__ __nv_bfloat16 g_eOut_hi[2 * NZ * 2 * NHE];
__device__ __nv_bfloat16 g_eOut_lo[2 * NZ * 2 * NHE];
__device__ __nv_bfloat16 g_initW_hi[2 * NHD * NZ];
__device__ __nv_bfloat16 g_initW_lo[2 * NHD * NZ];
__device__ __nv_bfloat16 g_zW_hi[NGD * NZ];
__device__ __nv_bfloat16 g_zW_lo[NGD * NZ];
__device__ __nv_bfloat16 g_outW_hi[NOUTD * NHD];
__device__ __nv_bfloat16 g_outW_lo[NOUTD * NHD];
__device__ float2 g_dWih2[NGD];

__device__ __nv_bfloat16 g_hn_hi[NB * 2 * NHE];
__device__ __nv_bfloat16 g_hn_lo[NB * 2 * NHE];
__device__ float g_ce[2 * NB * NHE];
__device__ float g_Ge[2 * NB * NGE];
__device__ float g_zml[NB * 2 * NZ];
__device__ __nv_bfloat16 g_z_hi[NB * NZ];
__device__ __nv_bfloat16 g_z_lo[NB * NZ];
__device__ float g_init[NB * 2 * NHD];
__device__ __nv_bfloat16 g_h0_hi[NB * NHD];
__device__ __nv_bfloat16 g_h0_lo[NB * NHD];
__device__ float g_cd[NB * NHD];
__device__ float g_zp[NB * NGD];
__device__ float g_G[NB * NGD];
__device__ __nv_bfloat16 g_hs_hi[(size_t)NB * NT * NHD];
__device__ __nv_bfloat16 g_hs_lo[(size_t)NB * NT * NHD];

// ---------------- helpers ----------------
__device__ __forceinline__ uint32_t smem_u32(const void* p) {
  uint32_t a;
  asm("{ .reg .u64 t; cvta.to.shared.u64 t, %1; cvt.u32.u64 %0, t; }" : "=r"(a) : "l"(p));
  return a;
}
__device__ __forceinline__ void cp16(uint32_t dst, const void* src, bool ok) {
  int sz = ok ? 16 : 0;
  asm volatile("cp.async.cg.shared.global [%0], [%1], 16, %2;\n"
               :: "r"(dst), "l"(src), "r"(sz) : "memory");
}
__device__ __forceinline__ void cp_commit() { asm volatile("cp.async.commit_group;" ::: "memory"); }
template <int N>
__device__ __forceinline__ void cp_wait() { asm volatile("cp.async.wait_group %0;" :: "n"(N) : "memory"); }

__device__ __forceinline__ float sigf(float x) {
  return __fdividef(1.0f, 1.0f + __expf(-x));
}
__device__ __forceinline__ float tanhfast(float x) {
  return 2.0f * sigf(2.0f * x) - 1.0f;
}
__device__ __forceinline__ void split_bf16(float x, __nv_bfloat16* hi, __nv_bfloat16* lo) {
  __nv_bfloat16 h = __float2bfloat16(x);
  *hi = h;
  *lo = __float2bfloat16(x - __bfloat162float(h));
}

struct GArg {
  const __nv_bfloat16 *Ahi, *Alo;  // [M][K] stride lda
  const __nv_bfloat16 *Whi, *Wlo;  // [N][K] packed
  const float *bias;
  const float *Cadd;
  float *C;
};

#define GS 197632u           // TN=256/S=4: 1024 + 4*49152
#define GS128 132096u        // TN=128/S=4: 1024 + 4*32768

#if USE_TC
// =====================================================================
// tcgen05 path — KC=32/SW64 4-stage pipelined GEMM (R11 proven config)
// =====================================================================
__device__ __forceinline__ uint32_t elect_one_pred() {
  uint32_t pred;
  asm volatile(
      "{\n\t.reg .pred p;\n\telect.sync _|p, 0xFFFFFFFF;\n\tselp.b32 %0, 1, 0, p;\n\t}"
      : "=r"(pred));
  return pred;
}
#define MBARRIER_INIT(addr, cnt) \
  asm volatile("mbarrier.init.shared.b64 [%0], %1;" :: "r"((uint32_t)(addr)), "r"((uint32_t)(cnt)) : "memory")
#define MBARRIER_WAIT_PARITY(addr, par) do {                                        \
  uint32_t _m = (uint32_t)(addr); uint32_t _p = (uint32_t)(par);                    \
  asm volatile("{\n\t.reg .pred P1;\n\t"                                            \
    "WL_%=:\n\t"                                                                    \
    "mbarrier.try_wait.parity.acquire.cta.shared::cta.b64 P1, [%0], %1, 0x989680;\n\t" \
    "@P1 bra.uni WD_%=;\n\t"                                                        \
    "bra.uni WL_%=;\n\t"                                                            \
    "WD_%=:\n\t}" :: "r"(_m), "r"(_p) : "memory");                                  \
} while (0)

#define TCGEN05_ALLOC(sm, n) \
  asm volatile("tcgen05.alloc.cta_group::1.sync.aligned.shared::cta.b32 [%0], %1;" \
               :: "r"((uint32_t)(sm)), "r"((uint32_t)(n)) : "memory")
#define TCGEN05_DEALLOC(t, n) \
  asm volatile("tcgen05.dealloc.cta_group::1.sync.aligned.b32 %0, %1;" :: "r"(t), "r"((uint32_t)(n)))
#define TCGEN05_RELINQ() \
  asm volatile("tcgen05.relinquish_alloc_permit.cta_group::1.sync.aligned;")
#define TCGEN05_COMMIT(mb) \
  asm volatile("tcgen05.commit.cta_group::1.mbarrier::arrive::one.shared::cluster.b64 [%0];" \
               :: "r"((uint32_t)(mb)) : "memory")
#define TCGEN05_FENCE_AFTER()  asm volatile("tcgen05.fence::after_thread_sync;" ::: "memory")
#define TCGEN05_FENCE_BEFORE() asm volatile("tcgen05.fence::before_thread_sync;" ::: "memory")
#define TCGEN05_WAIT_LD()      asm volatile("tcgen05.wait::ld.sync.aligned;" ::: "memory")
#define TCGEN05_LD_32X32B_X32(r, addr)                                            \
  asm volatile(                                                                   \
      "tcgen05.ld.sync.aligned.32x32b.x32.b32 "                                   \
      "{%0, %1, %2, %3, %4, %5, %6, %7, %8, %9, %10, %11, %12, %13, %14, %15, "   \
      " %16, %17, %18, %19, %20, %21, %22, %23, %24, %25, %26, %27, %28, %29, %30, %31}, [%32];" \
      : "=r"((r)[0]), "=r"((r)[1]), "=r"((r)[2]), "=r"((r)[3]),                   \
        "=r"((r)[4]), "=r"((r)[5]), "=r"((r)[6]), "=r"((r)[7]),                   \
        "=r"((r)[8]), "=r"((r)[9]), "=r"((r)[10]), "=r"((r)[11]),                 \
        "=r"((r)[12]), "=r"((r)[13]), "=r"((r)[14]), "=r"((r)[15]),               \
        "=r"((r)[16]), "=r"((r)[17]), "=r"((r)[18]), "=r"((r)[19]),               \
        "=r"((r)[20]), "=r"((r)[21]), "=r"((r)[22]), "=r"((r)[23]),               \
        "=r"((r)[24]), "=r"((r)[25]), "=r"((r)[26]), "=r"((r)[27]),               \
        "=r"((r)[28]), "=r"((r)[29]), "=r"((r)[30]), "=r"((r)[31])                \
      : "r"(addr))

static constexpr unsigned long long SMEM_DESC_BASE_SW64 =
    (4ull << 61) | (1ull << 46) | (32ull << 32) | (1ull << 16);
#define MAKE_SMEM_DESC64(a) (SMEM_DESC_BASE_SW64 | ((unsigned long long)((a) >> 4) & 0x3FFF))

template <int TN>
__device__ __forceinline__ void mma_cg1(uint32_t d, unsigned long long a,
                                        unsigned long long b, uint32_t en) {
  constexpr uint32_t idesc =
      (1u << 4) | (1u << 7) | (1u << 10) | ((TN / 8u) << 17) | (8u << 24);
  asm volatile(
      "{\n\t.reg .pred p;\n\tsetp.ne.u32 p, %4, 0;\n\t"
      "tcgen05.mma.cta_group::1.kind::f16 [%0], %1, %2, %3, {%5, %5, %5, %5}, p;\n\t}"
      :: "r"(d), "l"(a), "l"(b), "r"(idesc), "r"(en), "r"(0u) : "memory");
}

// KC=32/SW64 stage: Ahi@0(8K), Alo@8K, Bhi@16K(TN*64), Blo after
template <int TN>
__device__ __forceinline__ void load_stageP(
    uint32_t sbase, int stage, int ci, const GArg& g,
    size_t lda, int m0, int n0, int N, int K, int tid)
{
  const uint32_t stb = 16384u + (uint32_t)TN * 128u;
  const uint32_t base = sbase + (uint32_t)stage * stb;
  const int k0 = ci << 5;
#pragma unroll
  for (int it = 0; it < 2; ++it) {   // A: 128 rows x 4 chunks = 512
    int idx = tid + (it << 8);
    int row = idx >> 2, c = idx & 3;
    uint32_t off = (uint32_t)((row << 6) + (c << 4));
    off ^= ((off >> 3) & 0x30);
    size_t so = (size_t)(m0 + row) * lda + (size_t)k0 + (c << 3);
    cp16(base + off, g.Ahi + so, true);
    cp16(base + 8192u + off, g.Alo + so, true);
  }
#pragma unroll
  for (int it = 0; it < TN / 64; ++it) {  // B: TN rows x 4 chunks
    int idx = tid + (it << 8);
    int row = idx >> 2, c = idx & 3;
    int n = n0 + row;
    bool ok = (n < N);
    uint32_t off = (uint32_t)((row << 6) + (c << 4));
    off ^= ((off >> 3) & 0x30);
    size_t so = (size_t)(ok ? n : 0) * (size_t)K + (size_t)k0 + (c << 3);
    cp16(base + 16384u + off, g.Whi + so, ok);
    cp16(base + 16384u + (uint32_t)TN * 64u + off, g.Wlo + so, ok);
  }
  cp_commit();
}

template <int TN>
__device__ __forceinline__ void mma_chunkP(uint32_t sbase, int stage,
                                           uint32_t tmem, bool first) {
  const uint32_t stb = 16384u + (uint32_t)TN * 128u;
  uint32_t base = sbase + (uint32_t)stage * stb;
  unsigned long long dAh = MAKE_SMEM_DESC64(base);
  unsigned long long dAl = MAKE_SMEM_DESC64(base + 8192u);
  unsigned long long dBh = MAKE_SMEM_DESC64(base + 16384u);
  unsigned long long dBl = MAKE_SMEM_DESC64(base + 16384u + (uint32_t)TN * 64u);
#pragma unroll
  for (int ks = 0; ks < 2; ++ks) {
    unsigned long long o = (unsigned long long)(2 * ks);
    mma_cg1<TN>(tmem, dAh + o, dBh + o, (first && ks == 0) ? 0u : 1u);
    mma_cg1<TN>(tmem, dAh + o, dBl + o, 1u);
    mma_cg1<TN>(tmem, dAl + o, dBh + o, 1u);
  }
}

template <int TN>
__global__ void __launch_bounds__(256) gemm3(GArg a0, GArg a1, size_t lda,
                                             size_t ldc, int N, int K) {
  extern __shared__ __align__(1024) char smem[];
  const int tid = threadIdx.x;
  const uint32_t sb = smem_u32(smem);
  const GArg g = blockIdx.z ? a1 : a0;
  const int m0 = blockIdx.y * 128;
  const int n0 = blockIdx.x * TN;
  const int nch = K >> 5;            // K multiple of 32, nch >= 4

  if (tid == 0)
    for (int s = 0; s < 4; ++s) MBARRIER_INIT(sb + 16 + 8 * s, 1);
  if (tid < 32) TCGEN05_ALLOC(sb, TN);
  __syncthreads();
  uint32_t tmem;
  asm volatile("ld.shared.b32 %0, [%1];" : "=r"(tmem) : "r"(sb));

  GRID_SYNC();                        // wait for producer before reading A/W

  load_stageP<TN>(sb + 1024u, 0, 0, g, lda, m0, n0, N, K, tid);
  load_stageP<TN>(sb + 1024u, 1, 1, g, lda, m0, n0, N, K, tid);
  load_stageP<TN>(sb + 1024u, 2, 2, g, lda, m0, n0, N, K, tid);

  for (int i = 0; i < nch; ++i) {
    const int s = i & 3;
    if (i >= 1) {                    // delayed issue: load chunk i+2
      int nc = i + 2;
      if (nc < nch) {
        if (nc >= 4) MBARRIER_WAIT_PARITY(sb + 16 + 8 * (nc & 3), ((nc - 4) >> 2) & 1);
        load_stageP<TN>(sb + 1024u, nc & 3, nc, g, lda, m0, n0, N, K, tid);
      } else cp_commit();
    }
    cp_wait<2>();
    asm volatile("fence.proxy.async.shared::cta;" ::: "memory");
    __syncthreads();
    if (tid < 32 && elect_one_pred()) {
      mma_chunkP<TN>(sb + 1024u, s, tmem, i == 0);
      TCGEN05_COMMIT(sb + 16 + 8 * s);
    }
  }
  MBARRIER_WAIT_PARITY(sb + 16 + 8 * ((nch - 1) & 3), ((nch - 1) >> 2) & 1);
  GRID_TRIG();                        // successor may launch; epilogue remains
  TCGEN05_FENCE_AFTER();

  {
    const int wq = (tid >> 5) & 3, wg = tid >> 7, lane = tid & 31;
    const size_t m = (size_t)m0 + (size_t)(wq * 32 + lane);
    float* crow = g.C + m * ldc;
    const float* arow = g.Cadd ? (g.Cadd + m * ldc) : (const float*)0;
    for (int c0 = wg * (TN / 2); c0 < (wg + 1) * (TN / 2); c0 += 32) {
      int n = n0 + c0;
      if (n >= N) break;
      uint32_t r[32];
      TCGEN05_LD_32X32B_X32(r, tmem + c0);
      TCGEN05_WAIT_LD();
      if (((ldc & 3) == 0) && (n + 32 <= N)) {
#pragma unroll
        for (int q = 0; q < 8; ++q) {
          float4 v;
          v.x = __uint_as_float(r[4 * q + 0]);
          v.y = __uint_as_float(r[4 * q + 1]);
          v.z = __uint_as_float(r[4 * q + 2]);
          v.w = __uint_as_float(r[4 * q + 3]);
          if (g.bias) {
            float4 bv = *(const float4*)(g.bias + n + 4 * q);
            v.x += bv.x; v.y += bv.y; v.z += bv.z; v.w += bv.w;
          }
          if (arow) {
            float4 av = *(const float4*)(arow + n + 4 * q);
            v.x += av.x; v.y += av.y; v.z += av.z; v.w += av.w;
          }
          *(float4*)(crow + n + 4 * q) = v;
        }
      } else {
        for (int j = 0; j < 32 && n + j < N; ++j) {
          float v = __uint_as_float(r[j]);
          if (g.bias) v += g.bias[n + j];
          if (arow) v += arow[n + j];
          crow[n + j] = v;
        }
      }
    }
    TCGEN05_FENCE_BEFORE();
  }
  __syncthreads();
  if (tid < 32) { TCGEN05_RELINQ(); TCGEN05_DEALLOC(tmem, TN); }
}

#else
// =====================================================================
// Naive fallback (sm_103 non-a pass; never selected at runtime)
// =====================================================================
template <int TN>
__global__ void __launch_bounds__(256) gemm3(GArg a0, GArg a1, size_t lda,
                                             size_t ldc, int N, int K) {
  const GArg g = blockIdx.z ? a1 : a0;
  int m0 = blockIdx.y * 128, n0 = blockIdx.x * TN;
  GRID_SYNC();
  for (int e = threadIdx.x; e < 128 * TN; e += 256) {
    int m = m0 + e / TN, n = n0 + e % TN;
    if (n >= N) continue;
    float s = 0.f;
    const __nv_bfloat16 *ah = g.Ahi + (size_t)m * lda, *al = g.Alo + (size_t)m * lda;
    const __nv_bfloat16 *wh = g.Whi + (size_t)n * K, *wl = g.Wlo + (size_t)n * K;
    for (int k = 0; k < K; ++k)
      s += (__bfloat162float(ah[k]) + __bfloat162float(al[k])) *
           (__bfloat162float(wh[k]) + __bfloat162float(wl[k]));
    if (g.bias) s += g.bias[n];
    if (g.Cadd) s += g.Cadd[(size_t)m * ldc + n];
    g.C[(size_t)m * ldc + n] = s;
  }
  GRID_TRIG();
}
#endif  // USE_TC

// ---------------- cvt_all ----------------
#define SEG0 16777216L
#define SEG1 (SEG0 + 1048576L)
#define SEG2 (SEG1 + 1048576L)
#define SEG3 (SEG2 + 262144L)
#define SEG4 (SEG3 + 524288L)
#define SEG5 (SEG4 + 1048576L)
#define SEG6 (SEG5 + 251904L)
#define SEG7 (SEG6 + 524288L)
#define SEG8 (SEG7 + 8192L)
__global__ void cvt_all(const float* __restrict__ dWhh, const float* __restrict__ eWf,
                        const float* __restrict__ eWb, const float* __restrict__ eOut,
                        const float* __restrict__ initW, const float* __restrict__ decWih,
                        const float* __restrict__ outW) {
  long idx = blockIdx.x * 256L + threadIdx.x;
  if (idx >= SEG8) return;
  if (idx < SEG0) {
    split_bf16(dWhh[idx], &g_dWhh_hi[idx], &g_dWhh_lo[idx]);
  } else if (idx < SEG1) {
    long i = idx - SEG0; split_bf16(eWf[i], &g_eWf_hi[i], &g_eWf_lo[i]);
  } else if (idx < SEG2) {
    long i = idx - SEG1; split_bf16(eWb[i], &g_eWb_hi[i], &g_eWb_lo[i]);
  } else if (idx < SEG3) {
    long i = idx - SEG2; split_bf16(eOut[i], &g_eOut_hi[i], &g_eOut_lo[i]);
  } else if (idx < SEG4) {
    long i = idx - SEG3; split_bf16(initW[i], &g_initW_hi[i], &g_initW_lo[i]);
  } else if (idx < SEG5) {
    long i = idx - SEG4;
    long n = i >> 7, k = i & 127;
    split_bf16(decWih[n * DLD + 5 + k], &g_zW_hi[i], &g_zW_lo[i]);
  } else if (idx < SEG6) {
    long i = idx - SEG5; split_bf16(outW[i], &g_outW_hi[i], &g_outW_lo[i]);
  } else if (idx < SEG7) {
    long i = idx - SEG6;
    g_hn_hi[i] = __float2bfloat16(0.0f);
    g_hn_lo[i] = __float2bfloat16(0.0f);
    g_ce[i] = 0.0f;
  } else {
    int r = (int)(idx - SEG7);
    g_dWih2[r] = make_float2(decWih[(long)r * DLD], decWih[(long)r * DLD + 1]);
  }
}

// ---------------- gate / small kernels ----------------
__global__ void enc_gate_kernel(const float* __restrict__ data,
                                const int* __restrict__ lengths,
                                const float* __restrict__ Wih_f,
                                const float* __restrict__ Wih_b, int t) {
  GRID_TRIG();                        // successor prologue may overlap
  int idx = blockIdx.x * blockDim.x + threadIdx.x;
  int dir = idx >> 18;
  int rr = idx & ((1 << 18) - 1);
  int b = rr >> 9;
  int j = rr & 511;
  int L = lengths[b];
  L = L < 1 ? 1 : (L > NT ? NT : L);
  if (t >= L) return;
  int ti = dir ? (L - 1 - t) : t;
  float x0 = data[((size_t)b * DATALD + ti + 1) * 2 + 0];
  float x1 = data[((size_t)b * DATALD + ti + 1) * 2 + 1];
  const float* Wih = dir ? Wih_b : Wih_f;
  float wi0 = Wih[2 * j],                 wi1 = Wih[2 * j + 1];
  float wf0 = Wih[2 * (NHE + j)],         wf1 = Wih[2 * (NHE + j) + 1];
  float wg0 = Wih[2 * (2 * NHE + j)],     wg1 = Wih[2 * (2 * NHE + j) + 1];
  float wo0 = Wih[2 * (3 * NHE + j)],     wo1 = Wih[2 * (3 * NHE + j) + 1];
  GRID_SYNC();                        // producer GEMM must be done for G
  const float* G = g_Ge + (size_t)(dir * NB + b) * NGE;
  float pi = G[j]           + x0 * wi0 + x1 * wi1;
  float pf = G[NHE + j]     + x0 * wf0 + x1 * wf1;
  float pg = G[2 * NHE + j] + x0 * wg0 + x1 * wg1;
  float po = G[3 * NHE + j] + x0 * wo0 + x1 * wo1;
  int ci = (dir * NB + b) * NHE + j;
  float c = g_ce[ci];
  float c2 = sigf(pf) * c + sigf(pi) * tanhfast(pg);
  float h2 = sigf(po) * tanhfast(c2);
  g_ce[ci] = c2;
  int hidx = b * (2 * NHE) + dir * NHE + j;
  split_bf16(h2, &g_hn_hi[hidx], &g_hn_lo[hidx]);
}

__global__ void latent_kernel(const float* __restrict__ eps,
                              float* __restrict__ zm_out,
                              float* __restrict__ zl_out) {
  GRID_SYNC();
  int idx = blockIdx.x * blockDim.x + threadIdx.x;
  int b = idx >> 7, k = idx & 127;
  float zm = g_zml[b * 256 + k];
  float zl = g_zml[b * 256 + 128 + k];
  zm_out[idx] = zm;
  zl_out[idx] = zl;
  float z = zm + expf(0.5f * zl) * eps[idx];
  split_bf16(z, &g_z_hi[idx], &g_z_lo[idx]);
  GRID_TRIG();
}

__global__ void initsplit_kernel() {
  GRID_SYNC();
  int idx = blockIdx.x * blockDim.x + threadIdx.x;
  int b = idx >> 11, j = idx & 2047;
  float h0 = tanhfast(g_init[b * (2 * NHD) + j]);
  float c0 = tanhfast(g_init[b * (2 * NHD) + NHD + j]);
  g_cd[idx] = c0;
  split_bf16(h0, &g_h0_hi[idx], &g_h0_lo[idx]);
  GRID_TRIG();
}

__global__ void dec_gate_kernel(const float* __restrict__ data, int t) {
  GRID_TRIG();                        // next GEMM may alloc/init early
  int idx = blockIdx.x * blockDim.x + threadIdx.x;   // 512*1024 threads
  int b = idx >> 10, jp = (idx & 1023) << 1;
  float x0 = data[((size_t)b * DATALD + t) * 2 + 0];
  float x1 = data[((size_t)b * DATALD + t) * 2 + 1];
  float4 wi = *(const float4*)(g_dWih2 + jp);
  float4 wf = *(const float4*)(g_dWih2 + NHD + jp);
  float4 wg = *(const float4*)(g_dWih2 + 2 * NHD + jp);
  float4 wo = *(const float4*)(g_dWih2 + 3 * NHD + jp);
  GRID_SYNC();                        // producer GEMM must be done for G
  const float* G = g_G + (size_t)b * NGD;
  float2 gi = *(const float2*)(G + jp);
  float2 gf = *(const float2*)(G + NHD + jp);
  float2 gg = *(const float2*)(G + 2 * NHD + jp);
  float2 go = *(const float2*)(G + 3 * NHD + jp);
  gi.x += x0 * wi.x + x1 * wi.y;  gi.y += x0 * wi.z + x1 * wi.w;
  gf.x += x0 * wf.x + x1 * wf.y;  gf.y += x0 * wf.z + x1 * wf.w;
  gg.x += x0 * wg.x + x1 * wg.y;  gg.y += x0 * wg.z + x1 * wg.w;
  go.x += x0 * wo.x + x1 * wo.y;  go.y += x0 * wo.z + x1 * wo.w;
  size_t cbase = (size_t)b * NHD + jp;
  float2 c = *(const float2*)(g_cd + cbase);
  float c20 = sigf(gf.x) * c.x + sigf(gi.x) * tanhfast(gg.x);
  float c21 = sigf(gf.y) * c.y + sigf(gi.y) * tanhfast(gg.y);
  float h20 = sigf(go.x) * tanhfast(c20);
  float h21 = sigf(go.y) * tanhfast(c21);
  *(float2*)(g_cd + cbase) = make_float2(c20, c21);
  size_t ho = ((size_t)b * NT + t) * NHD + jp;
  __nv_bfloat16 hh0, hl0, hh1, hl1;
  split_bf16(h20, &hh0, &hl0);
  split_bf16(h21, &hh1, &hl1);
  *(__nv_bfloat162*)(g_hs_hi + ho) = __nv_bfloat162(hh0, hh1);
  *(__nv_bfloat162*)(g_hs_lo + ho) = __nv_bfloat162(hl0, hl1);
}

// ---------------- PDL launch helper ----------------
template <typename F, typename... Args>
static inline void pdl_launch(F* f, dim3 grid, dim3 block, size_t smem, Args... args) {
  cudaLaunchConfig_t cfg = {};
  cfg.gridDim = grid;
  cfg.blockDim = block;
  cfg.dynamicSmemBytes = smem;
  cfg.stream = 0;
  cudaLaunchAttribute at[1];
  at[0].id = cudaLaunchAttributeProgrammaticStreamSerialization;
  at[0].val.programmaticStreamSerializationAllowed = 1;
  cfg.attrs = at;
  cfg.numAttrs = 1;
  cudaLaunchKernelEx(&cfg, f, args...);
}

static inline void run_gemm(const GArg& a0, const GArg& a1, size_t lda, size_t ldc,
                            int N, int K, int M, int nz) {
  dim3 grid((unsigned)((N + 127) / 128), (unsigned)(M / 128), (unsigned)nz);
  pdl_launch(gemm3<128>, grid, dim3(256), (size_t)GS128, a0, a1, lda, ldc, N, K);
}

extern "C" void kernel_launch(void* const* d_in, const int* in_sizes, int n_in,
                              void* d_out, int out_size) {
  const float* data      = (const float*)d_in[0];
  const float* eps       = (const float*)d_in[1];
  const float* enc_Wih_f = (const float*)d_in[2];
  const float* enc_Whh_f = (const float*)d_in[3];
  const float* enc_b_f   = (const float*)d_in[4];
  const float* enc_Wih_b = (const float*)d_in[5];
  const float* enc_Whh_b = (const float*)d_in[6];
  const float* enc_b_b   = (const float*)d_in[7];
  const float* enc_out_W = (const float*)d_in[8];
  const float* enc_out_b = (const float*)d_in[9];
  const float* init_W    = (const float*)d_in[10];
  const float* init_b    = (const float*)d_in[11];
  const float* dec_Wih   = (const float*)d_in[12];
  const float* dec_Whh   = (const float*)d_in[13];
  const float* dec_b     = (const float*)d_in[14];
  const float* out_W     = (const float*)d_in[15];
  const float* out_b     = (const float*)d_in[16];
  const int*   lengths   = (const int*)d_in[17];

  float* out    = (float*)d_out;
  float* params = out;
  float* zm_out = out + (size_t)NB * NT * NOUTD;
  float* zl_out = zm_out + (size_t)NB * NT;

  cudaFuncSetAttribute(gemm3<128>, cudaFuncAttributeMaxDynamicSharedMemorySize, GS128);
  cudaFuncSetAttribute(gemm3<256>, cudaFuncAttributeMaxDynamicSharedMemorySize, GS);

#define SYM(p, s) cudaGetSymbolAddress((void**)&p, s)
  __nv_bfloat16 *dWhh_hi, *dWhh_lo, *eWf_hi, *eWf_lo, *eWb_hi, *eWb_lo;
  __nv_bfloat16 *eOut_hi, *eOut_lo, *initW_hi, *initW_lo, *zW_hi, *zW_lo, *outW_hi, *outW_lo;
  __nv_bfloat16 *hn_hi, *hn_lo, *z_hi, *z_lo, *h0_hi, *h0_lo, *hs_hi, *hs_lo;
  float *Ge, *zml, *initb, *zp, *G;
  SYM(dWhh_hi, g_dWhh_hi); SYM(dWhh_lo, g_dWhh_lo);
  SYM(eWf_hi, g_eWf_hi); SYM(eWf_lo, g_eWf_lo);
  SYM(eWb_hi, g_eWb_hi); SYM(eWb_lo, g_eWb_lo);
  SYM(eOut_hi, g_eOut_hi); SYM(eOut_lo, g_eOut_lo);
  SYM(initW_hi, g_initW_hi); SYM(initW_lo, g_initW_lo);
  SYM(zW_hi, g_zW_hi); SYM(zW_lo, g_zW_lo);
  SYM(outW_hi, g_outW_hi); SYM(outW_lo, g_outW_lo);
  SYM(hn_hi, g_hn_hi); SYM(hn_lo, g_hn_lo);
  SYM(z_hi, g_z_hi); SYM(z_lo, g_z_lo);
  SYM(h0_hi, g_h0_hi); SYM(h0_lo, g_h0_lo);
  SYM(hs_hi, g_hs_hi); SYM(hs_lo, g_hs_lo);
  SYM(Ge, g_Ge); SYM(zml, g_zml); SYM(initb, g_init); SYM(zp, g_zp); SYM(G, g_G);
#undef SYM

  cvt_all<<<(unsigned)((SEG8 + 255) / 256), 256>>>(
      dec_Whh, enc_Whh_f, enc_Whh_b, enc_out_W, init_W, dec_Wih, out_W);

  // ---- bidirectional encoder, 128 steps (TN=128, S=4, LOOK=2) ----
  for (int t = 0; t < NT; t++) {
    GArg f = {hn_hi, hn_lo, eWf_hi, eWf_lo, enc_b_f, nullptr, Ge};
    GArg bw = {hn_hi + NHE, hn_lo + NHE, eWb_hi, eWb_lo, enc_b_b, nullptr,
               Ge + (size_t)NB * NGE};
    run_gemm(f, bw, 2 * NHE, NGE, NGE, NHE, NB, 2);
    pdl_launch(enc_gate_kernel, dim3(2048), dim3(256), (size_t)0,
               data, lengths, enc_Wih_f, enc_Wih_b, t);
  }

  // ---- latent ----
  {
    GArg a = {hn_hi, hn_lo, eOut_hi, eOut_lo, enc_out_b, nullptr, zml};
    run_gemm(a, a, 2 * NHE, 2 * NZ, 2 * NZ, 2 * NHE, NB, 1);
  }
  pdl_launch(latent_kernel, dim3(256), dim3(256), (size_t)0, eps, zm_out, zl_out);
  {
    GArg a = {z_hi, z_lo, initW_hi, initW_lo, init_b, nullptr, initb};
    run_gemm(a, a, NZ, 2 * NHD, 2 * NHD, NZ, NB, 1);
  }
  pdl_launch(initsplit_kernel, dim3(4096), dim3(256), (size_t)0);
  {
    GArg a = {z_hi, z_lo, zW_hi, zW_lo, dec_b, nullptr, zp};
    run_gemm(a, a, NZ, NGD, NGD, NZ, NB, 1);
  }

  // ---- decoder, 128 steps (TN=256, S=4, LOOK=2 + gate) ----
  for (int t = 0; t < NT; t++) {
    const __nv_bfloat16* Ah = t ? (hs_hi + (size_t)(t - 1) * NHD) : h0_hi;
    const __nv_bfloat16* Al = t ? (hs_lo + (size_t)(t - 1) * NHD) : h0_lo;
    size_t lda = t ? (size_t)NT * NHD : (size_t)NHD;
    GArg a = {Ah, Al, dWhh_hi, dWhh_lo, nullptr, zp, G};
    pdl_launch(gemm3<256>, dim3(32, 4), dim3(256), (size_t)GS,
               a, a, lda, (size_t)NGD, NGD, NHD);
    pdl_launch(dec_gate_kernel, dim3(2048), dim3(256), (size_t)0, data, t);
  }

  // ---- output projection ----
  {
    GArg a = {hs_hi, hs_lo, outW_hi, outW_lo, out_b, nullptr, params};
    run_gemm(a, a, NHD, NOUTD, NOUTD, NHD, NB * NT, 1);
  }
}

// round 16
// speedup vs baseline: 1.1260x; 1.0169x over previous
#include <cuda_runtime.h>
#include <cuda_bf16.h>
#include <math.h>
#include <stdint.h>

#define NB 512
#define NT 128
#define NHE 512
#define NGE 2048
#define NZ 128
#define NHD 2048
#define NGD 8192
#define NOUTD 123
#define DATALD 129
#define DLD 133

#if !defined(__CUDA_ARCH__)
#define USE_TC 1
#elif defined(__CUDA_ARCH_FEAT_SM103_ALL) || defined(__CUDA_ARCH_FEAT_SM100_ALL)
#define USE_TC 1
#else
#define USE_TC 0
#endif

#if defined(__CUDA_ARCH__) && (__CUDA_ARCH__ >= 900)
#define GRID_SYNC() cudaGridDependencySynchronize()
#define GRID_TRIG() cudaTriggerProgrammaticLaunchCompletion()
#else
#define GRID_SYNC()
#define GRID_TRIG()
#endif

// ---------------- device scratch ----------------
__device__ __nv_bfloat16 g_dWhh_hi[NGD * NHD];
__device__ __nv_bfloat16 g_dWhh_lo[NGD * NHD];
__device__ __nv_bfloat16 g_eWf_hi[NGE * NHE];
__device__ __nv_bfloat16 g_eWf_lo[NGE * NHE];
__device__ __nv_bfloat16 g_eWb_hi[NGE * NHE];
__device__ __nv_bfloat16 g_eWb_lo[NGE * NHE];
__device__ __nv_bfloat16 g_eOut_hi[2 * NZ * 2 * NHE];
__device__ __nv_bfloat16 g_eOut_lo[2 * NZ * 2 * NHE];
__device__ __nv_bfloat16 g_initW_hi[2 * NHD * NZ];
__device__ __nv_bfloat16 g_initW_lo[2 * NHD * NZ];
__device__ __nv_bfloat16 g_zW_hi[NGD * NZ];
__device__ __nv_bfloat16 g_zW_lo[NGD * NZ];
__device__ __nv_bfloat16 g_outW_hi[NOUTD * NHD];
__device__ __nv_bfloat16 g_outW_lo[NOUTD * NHD];
__device__ float2 g_dWih2[NGD];

__device__ __nv_bfloat16 g_hn_hi[NB * 2 * NHE];
__device__ __nv_bfloat16 g_hn_lo[NB * 2 * NHE];
__device__ float g_ce[2 * NB * NHE];
__device__ float g_Ge[2 * NB * NGE];
__device__ float g_zml[NB * 2 * NZ];
__device__ __nv_bfloat16 g_z_hi[NB * NZ];
__device__ __nv_bfloat16 g_z_lo[NB * NZ];
__device__ float g_init[NB * 2 * NHD];
__device__ __nv_bfloat16 g_h0_hi[NB * NHD];
__device__ __nv_bfloat16 g_h0_lo[NB * NHD];
__device__ float g_cd[NB * NHD];
__device__ float g_zp[NB * NGD];
__device__ float g_G[NB * NGD];
__device__ __nv_bfloat16 g_hs_hi[(size_t)NB * NT * NHD];
__device__ __nv_bfloat16 g_hs_lo[(size_t)NB * NT * NHD];

// ---------------- helpers ----------------
__device__ __forceinline__ uint32_t smem_u32(const void* p) {
  uint32_t a;
  asm("{ .reg .u64 t; cvta.to.shared.u64 t, %1; cvt.u32.u64 %0, t; }" : "=r"(a) : "l"(p));
  return a;
}
__device__ __forceinline__ void cp16(uint32_t dst, const void* src, bool ok) {
  int sz = ok ? 16 : 0;
  asm volatile("cp.async.cg.shared.global [%0], [%1], 16, %2;\n"
               :: "r"(dst), "l"(src), "r"(sz) : "memory");
}
__device__ __forceinline__ void cp_commit() { asm volatile("cp.async.commit_group;" ::: "memory"); }
template <int N>
__device__ __forceinline__ void cp_wait() { asm volatile("cp.async.wait_group %0;" :: "n"(N) : "memory"); }

__device__ __forceinline__ float sigf(float x) {
  return __fdividef(1.0f, 1.0f + __expf(-x));
}
__device__ __forceinline__ float tanhfast(float x) {
  return 2.0f * sigf(2.0f * x) - 1.0f;
}
__device__ __forceinline__ void split_bf16(float x, __nv_bfloat16* hi, __nv_bfloat16* lo) {
  __nv_bfloat16 h = __float2bfloat16(x);
  *hi = h;
  *lo = __float2bfloat16(x - __bfloat162float(h));
}

struct GArg {
  const __nv_bfloat16 *Ahi, *Alo;  // [M][K] stride lda
  const __nv_bfloat16 *Whi, *Wlo;  // [N][K] packed
  const float *bias;
  const float *Cadd;
  float *C;
};

#define GS 197632u           // TN=256/S=4: 1024 + 4*49152
#define GS128 132096u        // TN=128/S=4: 1024 + 4*32768

#if USE_TC
// =====================================================================
// tcgen05 path — KC=32/SW64 4-stage pipelined GEMM (R11 proven config)
// =====================================================================
__device__ __forceinline__ uint32_t elect_one_pred() {
  uint32_t pred;
  asm volatile(
      "{\n\t.reg .pred p;\n\telect.sync _|p, 0xFFFFFFFF;\n\tselp.b32 %0, 1, 0, p;\n\t}"
      : "=r"(pred));
  return pred;
}
#define MBARRIER_INIT(addr, cnt) \
  asm volatile("mbarrier.init.shared.b64 [%0], %1;" :: "r"((uint32_t)(addr)), "r"((uint32_t)(cnt)) : "memory")
#define MBARRIER_WAIT_PARITY(addr, par) do {                                        \
  uint32_t _m = (uint32_t)(addr); uint32_t _p = (uint32_t)(par);                    \
  asm volatile("{\n\t.reg .pred P1;\n\t"                                            \
    "WL_%=:\n\t"                                                                    \
    "mbarrier.try_wait.parity.acquire.cta.shared::cta.b64 P1, [%0], %1, 0x989680;\n\t" \
    "@P1 bra.uni WD_%=;\n\t"                                                        \
    "bra.uni WL_%=;\n\t"                                                            \
    "WD_%=:\n\t}" :: "r"(_m), "r"(_p) : "memory");                                  \
} while (0)

#define TCGEN05_ALLOC(sm, n) \
  asm volatile("tcgen05.alloc.cta_group::1.sync.aligned.shared::cta.b32 [%0], %1;" \
               :: "r"((uint32_t)(sm)), "r"((uint32_t)(n)) : "memory")
#define TCGEN05_DEALLOC(t, n) \
  asm volatile("tcgen05.dealloc.cta_group::1.sync.aligned.b32 %0, %1;" :: "r"(t), "r"((uint32_t)(n)))
#define TCGEN05_RELINQ() \
  asm volatile("tcgen05.relinquish_alloc_permit.cta_group::1.sync.aligned;")
#define TCGEN05_COMMIT(mb) \
  asm volatile("tcgen05.commit.cta_group::1.mbarrier::arrive::one.shared::cluster.b64 [%0];" \
               :: "r"((uint32_t)(mb)) : "memory")
#define TCGEN05_FENCE_AFTER()  asm volatile("tcgen05.fence::after_thread_sync;" ::: "memory")
#define TCGEN05_FENCE_BEFORE() asm volatile("tcgen05.fence::before_thread_sync;" ::: "memory")
#define TCGEN05_WAIT_LD()      asm volatile("tcgen05.wait::ld.sync.aligned;" ::: "memory")
#define TCGEN05_LD_32X32B_X32(r, addr)                                            \
  asm volatile(                                                                   \
      "tcgen05.ld.sync.aligned.32x32b.x32.b32 "                                   \
      "{%0, %1, %2, %3, %4, %5, %6, %7, %8, %9, %10, %11, %12, %13, %14, %15, "   \
      " %16, %17, %18, %19, %20, %21, %22, %23, %24, %25, %26, %27, %28, %29, %30, %31}, [%32];" \
      : "=r"((r)[0]), "=r"((r)[1]), "=r"((r)[2]), "=r"((r)[3]),                   \
        "=r"((r)[4]), "=r"((r)[5]), "=r"((r)[6]), "=r"((r)[7]),                   \
        "=r"((r)[8]), "=r"((r)[9]), "=r"((r)[10]), "=r"((r)[11]),                 \
        "=r"((r)[12]), "=r"((r)[13]), "=r"((r)[14]), "=r"((r)[15]),               \
        "=r"((r)[16]), "=r"((r)[17]), "=r"((r)[18]), "=r"((r)[19]),               \
        "=r"((r)[20]), "=r"((r)[21]), "=r"((r)[22]), "=r"((r)[23]),               \
        "=r"((r)[24]), "=r"((r)[25]), "=r"((r)[26]), "=r"((r)[27]),               \
        "=r"((r)[28]), "=r"((r)[29]), "=r"((r)[30]), "=r"((r)[31])                \
      : "r"(addr))

static constexpr unsigned long long SMEM_DESC_BASE_SW64 =
    (4ull << 61) | (1ull << 46) | (32ull << 32) | (1ull << 16);
#define MAKE_SMEM_DESC64(a) (SMEM_DESC_BASE_SW64 | ((unsigned long long)((a) >> 4) & 0x3FFF))

template <int TN>
__device__ __forceinline__ void mma_cg1(uint32_t d, unsigned long long a,
                                        unsigned long long b, uint32_t en) {
  constexpr uint32_t idesc =
      (1u << 4) | (1u << 7) | (1u << 10) | ((TN / 8u) << 17) | (8u << 24);
  asm volatile(
      "{\n\t.reg .pred p;\n\tsetp.ne.u32 p, %4, 0;\n\t"
      "tcgen05.mma.cta_group::1.kind::f16 [%0], %1, %2, %3, {%5, %5, %5, %5}, p;\n\t}"
      :: "r"(d), "l"(a), "l"(b), "r"(idesc), "r"(en), "r"(0u) : "memory");
}

// KC=32/SW64 stage: Ahi@0(8K), Alo@8K, Bhi@16K(TN*64), Blo after
template <int TN>
__device__ __forceinline__ void load_stageP(
    uint32_t sbase, int stage, int ci, const GArg& g,
    size_t lda, int m0, int n0, int N, int K, int tid)
{
  const uint32_t stb = 16384u + (uint32_t)TN * 128u;
  const uint32_t base = sbase + (uint32_t)stage * stb;
  const int k0 = ci << 5;
#pragma unroll
  for (int it = 0; it < 2; ++it) {   // A: 128 rows x 4 chunks = 512
    int idx = tid + (it << 8);
    int row = idx >> 2, c = idx & 3;
    uint32_t off = (uint32_t)((row << 6) + (c << 4));
    off ^= ((off >> 3) & 0x30);
    size_t so = (size_t)(m0 + row) * lda + (size_t)k0 + (c << 3);
    cp16(base + off, g.Ahi + so, true);
    cp16(base + 8192u + off, g.Alo + so, true);
  }
#pragma unroll
  for (int it = 0; it < TN / 64; ++it) {  // B: TN rows x 4 chunks
    int idx = tid + (it << 8);
    int row = idx >> 2, c = idx & 3;
    int n = n0 + row;
    bool ok = (n < N);
    uint32_t off = (uint32_t)((row << 6) + (c << 4));
    off ^= ((off >> 3) & 0x30);
    size_t so = (size_t)(ok ? n : 0) * (size_t)K + (size_t)k0 + (c << 3);
    cp16(base + 16384u + off, g.Whi + so, ok);
    cp16(base + 16384u + (uint32_t)TN * 64u + off, g.Wlo + so, ok);
  }
  cp_commit();
}

template <int TN>
__device__ __forceinline__ void mma_chunkP(uint32_t sbase, int stage,
                                           uint32_t tmem, bool first) {
  const uint32_t stb = 16384u + (uint32_t)TN * 128u;
  uint32_t base = sbase + (uint32_t)stage * stb;
  unsigned long long dAh = MAKE_SMEM_DESC64(base);
  unsigned long long dAl = MAKE_SMEM_DESC64(base + 8192u);
  unsigned long long dBh = MAKE_SMEM_DESC64(base + 16384u);
  unsigned long long dBl = MAKE_SMEM_DESC64(base + 16384u + (uint32_t)TN * 64u);
#pragma unroll
  for (int ks = 0; ks < 2; ++ks) {
    unsigned long long o = (unsigned long long)(2 * ks);
    mma_cg1<TN>(tmem, dAh + o, dBh + o, (first && ks == 0) ? 0u : 1u);
    mma_cg1<TN>(tmem, dAh + o, dBl + o, 1u);
    mma_cg1<TN>(tmem, dAl + o, dBh + o, 1u);
  }
}

template <int TN>
__global__ void __launch_bounds__(256) gemm3(GArg a0, GArg a1, size_t lda,
                                             size_t ldc, int N, int K) {
  extern __shared__ __align__(1024) char smem[];
  const int tid = threadIdx.x;
  const uint32_t sb = smem_u32(smem);
  const GArg g = blockIdx.z ? a1 : a0;
  const int m0 = blockIdx.y * 128;
  const int n0 = blockIdx.x * TN;
  const int nch = K >> 5;            // K multiple of 32, nch >= 4

  if (tid == 0)
    for (int s = 0; s < 4; ++s) MBARRIER_INIT(sb + 16 + 8 * s, 1);
  if (tid < 32) TCGEN05_ALLOC(sb, TN);
  __syncthreads();
  uint32_t tmem;
  asm volatile("ld.shared.b32 %0, [%1];" : "=r"(tmem) : "r"(sb));

  GRID_SYNC();                        // wait for producer before reading A/W
  GRID_TRIG();                        // successor may launch now: it becomes
                                      // resident, does independent loads, and
                                      // blocks in its own GRID_SYNC until we end

  load_stageP<TN>(sb + 1024u, 0, 0, g, lda, m0, n0, N, K, tid);
  load_stageP<TN>(sb + 1024u, 1, 1, g, lda, m0, n0, N, K, tid);
  load_stageP<TN>(sb + 1024u, 2, 2, g, lda, m0, n0, N, K, tid);

  for (int i = 0; i < nch; ++i) {
    const int s = i & 3;
    if (i >= 1) {                    // delayed issue: load chunk i+2
      int nc = i + 2;
      if (nc < nch) {
        if (nc >= 4) MBARRIER_WAIT_PARITY(sb + 16 + 8 * (nc & 3), ((nc - 4) >> 2) & 1);
        load_stageP<TN>(sb + 1024u, nc & 3, nc, g, lda, m0, n0, N, K, tid);
      } else cp_commit();
    }
    cp_wait<2>();
    asm volatile("fence.proxy.async.shared::cta;" ::: "memory");
    __syncthreads();
    if (tid < 32 && elect_one_pred()) {
      mma_chunkP<TN>(sb + 1024u, s, tmem, i == 0);
      TCGEN05_COMMIT(sb + 16 + 8 * s);
    }
  }
  MBARRIER_WAIT_PARITY(sb + 16 + 8 * ((nch - 1) & 3), ((nch - 1) >> 2) & 1);
  TCGEN05_FENCE_AFTER();

  {
    const int wq = (tid >> 5) & 3, wg = tid >> 7, lane = tid & 31;
    const size_t m = (size_t)m0 + (size_t)(wq * 32 + lane);
    float* crow = g.C + m * ldc;
    const float* arow = g.Cadd ? (g.Cadd + m * ldc) : (const float*)0;
    for (int c0 = wg * (TN / 2); c0 < (wg + 1) * (TN / 2); c0 += 32) {
      int n = n0 + c0;
      if (n >= N) break;
      uint32_t r[32];
      TCGEN05_LD_32X32B_X32(r, tmem + c0);
      TCGEN05_WAIT_LD();
      if (((ldc & 3) == 0) && (n + 32 <= N)) {
#pragma unroll
        for (int q = 0; q < 8; ++q) {
          float4 v;
          v.x = __uint_as_float(r[4 * q + 0]);
          v.y = __uint_as_float(r[4 * q + 1]);
          v.z = __uint_as_float(r[4 * q + 2]);
          v.w = __uint_as_float(r[4 * q + 3]);
          if (g.bias) {
            float4 bv = *(const float4*)(g.bias + n + 4 * q);
            v.x += bv.x; v.y += bv.y; v.z += bv.z; v.w += bv.w;
          }
          if (arow) {
            float4 av = *(const float4*)(arow + n + 4 * q);
            v.x += av.x; v.y += av.y; v.z += av.z; v.w += av.w;
          }
          *(float4*)(crow + n + 4 * q) = v;
        }
      } else {
        for (int j = 0; j < 32 && n + j < N; ++j) {
          float v = __uint_as_float(r[j]);
          if (g.bias) v += g.bias[n + j];
          if (arow) v += arow[n + j];
          crow[n + j] = v;
        }
      }
    }
    TCGEN05_FENCE_BEFORE();
  }
  __syncthreads();
  if (tid < 32) { TCGEN05_RELINQ(); TCGEN05_DEALLOC(tmem, TN); }
}

#else
// =====================================================================
// Naive fallback (sm_103 non-a pass; never selected at runtime)
// =====================================================================
template <int TN>
__global__ void __launch_bounds__(256) gemm3(GArg a0, GArg a1, size_t lda,
                                             size_t ldc, int N, int K) {
  const GArg g = blockIdx.z ? a1 : a0;
  int m0 = blockIdx.y * 128, n0 = blockIdx.x * TN;
  GRID_SYNC();
  GRID_TRIG();
  for (int e = threadIdx.x; e < 128 * TN; e += 256) {
    int m = m0 + e / TN, n = n0 + e % TN;
    if (n >= N) continue;
    float s = 0.f;
    const __nv_bfloat16 *ah = g.Ahi + (size_t)m * lda, *al = g.Alo + (size_t)m * lda;
    const __nv_bfloat16 *wh = g.Whi + (size_t)n * K, *wl = g.Wlo + (size_t)n * K;
    for (int k = 0; k < K; ++k)
      s += (__bfloat162float(ah[k]) + __bfloat162float(al[k])) *
           (__bfloat162float(wh[k]) + __bfloat162float(wl[k]));
    if (g.bias) s += g.bias[n];
    if (g.Cadd) s += g.Cadd[(size_t)m * ldc + n];
    g.C[(size_t)m * ldc + n] = s;
  }
}
#endif  // USE_TC

// ---------------- cvt_all ----------------
#define SEG0 16777216L
#define SEG1 (SEG0 + 1048576L)
#define SEG2 (SEG1 + 1048576L)
#define SEG3 (SEG2 + 262144L)
#define SEG4 (SEG3 + 524288L)
#define SEG5 (SEG4 + 1048576L)
#define SEG6 (SEG5 + 251904L)
#define SEG7 (SEG6 + 524288L)
#define SEG8 (SEG7 + 8192L)
__global__ void cvt_all(const float* __restrict__ dWhh, const float* __restrict__ eWf,
                        const float* __restrict__ eWb, const float* __restrict__ eOut,
                        const float* __restrict__ initW, const float* __restrict__ decWih,
                        const float* __restrict__ outW) {
  long idx = blockIdx.x * 256L + threadIdx.x;
  if (idx >= SEG8) return;
  if (idx < SEG0) {
    split_bf16(dWhh[idx], &g_dWhh_hi[idx], &g_dWhh_lo[idx]);
  } else if (idx < SEG1) {
    long i = idx - SEG0; split_bf16(eWf[i], &g_eWf_hi[i], &g_eWf_lo[i]);
  } else if (idx < SEG2) {
    long i = idx - SEG1; split_bf16(eWb[i], &g_eWb_hi[i], &g_eWb_lo[i]);
  } else if (idx < SEG3) {
    long i = idx - SEG2; split_bf16(eOut[i], &g_eOut_hi[i], &g_eOut_lo[i]);
  } else if (idx < SEG4) {
    long i = idx - SEG3; split_bf16(initW[i], &g_initW_hi[i], &g_initW_lo[i]);
  } else if (idx < SEG5) {
    long i = idx - SEG4;
    long n = i >> 7, k = i & 127;
    split_bf16(decWih[n * DLD + 5 + k], &g_zW_hi[i], &g_zW_lo[i]);
  } else if (idx < SEG6) {
    long i = idx - SEG5; split_bf16(outW[i], &g_outW_hi[i], &g_outW_lo[i]);
  } else if (idx < SEG7) {
    long i = idx - SEG6;
    g_hn_hi[i] = __float2bfloat16(0.0f);
    g_hn_lo[i] = __float2bfloat16(0.0f);
    g_ce[i] = 0.0f;
  } else {
    int r = (int)(idx - SEG7);
    g_dWih2[r] = make_float2(decWih[(long)r * DLD], decWih[(long)r * DLD + 1]);
  }
}

// ---------------- gate / small kernels ----------------
__global__ void enc_gate_kernel(const float* __restrict__ data,
                                const int* __restrict__ lengths,
                                const float* __restrict__ Wih_f,
                                const float* __restrict__ Wih_b, int t) {
  GRID_TRIG();                        // successor prologue may overlap
  int idx = blockIdx.x * blockDim.x + threadIdx.x;
  int dir = idx >> 18;
  int rr = idx & ((1 << 18) - 1);
  int b = rr >> 9;
  int j = rr & 511;
  int L = lengths[b];
  L = L < 1 ? 1 : (L > NT ? NT : L);
  bool act = (t < L);
  int ti = dir ? (L - 1 - t) : t;
  if (!act) ti = 0;
  float x0 = data[((size_t)b * DATALD + ti + 1) * 2 + 0];
  float x1 = data[((size_t)b * DATALD + ti + 1) * 2 + 1];
  const float* Wih = dir ? Wih_b : Wih_f;
  float wi0 = Wih[2 * j],                 wi1 = Wih[2 * j + 1];
  float wf0 = Wih[2 * (NHE + j)],         wf1 = Wih[2 * (NHE + j) + 1];
  float wg0 = Wih[2 * (2 * NHE + j)],     wg1 = Wih[2 * (2 * NHE + j) + 1];
  float wo0 = Wih[2 * (3 * NHE + j)],     wo1 = Wih[2 * (3 * NHE + j) + 1];
  GRID_SYNC();                        // producer GEMM must be done for G
  if (!act) return;
  const float* G = g_Ge + (size_t)(dir * NB + b) * NGE;
  float pi = G[j]           + x0 * wi0 + x1 * wi1;
  float pf = G[NHE + j]     + x0 * wf0 + x1 * wf1;
  float pg = G[2 * NHE + j] + x0 * wg0 + x1 * wg1;
  float po = G[3 * NHE + j] + x0 * wo0 + x1 * wo1;
  int ci = (dir * NB + b) * NHE + j;
  float c = g_ce[ci];
  float c2 = sigf(pf) * c + sigf(pi) * tanhfast(pg);
  float h2 = sigf(po) * tanhfast(c2);
  g_ce[ci] = c2;
  int hidx = b * (2 * NHE) + dir * NHE + j;
  split_bf16(h2, &g_hn_hi[hidx], &g_hn_lo[hidx]);
}

__global__ void latent_kernel(const float* __restrict__ eps,
                              float* __restrict__ zm_out,
                              float* __restrict__ zl_out) {
  GRID_SYNC();
  int idx = blockIdx.x * blockDim.x + threadIdx.x;
  int b = idx >> 7, k = idx & 127;
  float zm = g_zml[b * 256 + k];
  float zl = g_zml[b * 256 + 128 + k];
  zm_out[idx] = zm;
  zl_out[idx] = zl;
  float z = zm + expf(0.5f * zl) * eps[idx];
  split_bf16(z, &g_z_hi[idx], &g_z_lo[idx]);
  GRID_TRIG();
}

__global__ void initsplit_kernel() {
  GRID_SYNC();
  int idx = blockIdx.x * blockDim.x + threadIdx.x;
  int b = idx >> 11, j = idx & 2047;
  float h0 = tanhfast(g_init[b * (2 * NHD) + j]);
  float c0 = tanhfast(g_init[b * (2 * NHD) + NHD + j]);
  g_cd[idx] = c0;
  split_bf16(h0, &g_h0_hi[idx], &g_h0_lo[idx]);
  GRID_TRIG();
}

__global__ void dec_gate_kernel(const float* __restrict__ data, int t) {
  GRID_TRIG();                        // next GEMM may alloc/init early
  int idx = blockIdx.x * blockDim.x + threadIdx.x;   // 512*1024 threads
  int b = idx >> 10, jp = (idx & 1023) << 1;
  float x0 = data[((size_t)b * DATALD + t) * 2 + 0];
  float x1 = data[((size_t)b * DATALD + t) * 2 + 1];
  float4 wi = *(const float4*)(g_dWih2 + jp);
  float4 wf = *(const float4*)(g_dWih2 + NHD + jp);
  float4 wg = *(const float4*)(g_dWih2 + 2 * NHD + jp);
  float4 wo = *(const float4*)(g_dWih2 + 3 * NHD + jp);
  GRID_SYNC();                        // producer GEMM must be done for G
  const float* G = g_G + (size_t)b * NGD;
  float2 gi = *(const float2*)(G + jp);
  float2 gf = *(const float2*)(G + NHD + jp);
  float2 gg = *(const float2*)(G + 2 * NHD + jp);
  float2 go = *(const float2*)(G + 3 * NHD + jp);
  gi.x += x0 * wi.x + x1 * wi.y;  gi.y += x0 * wi.z + x1 * wi.w;
  gf.x += x0 * wf.x + x1 * wf.y;  gf.y += x0 * wf.z + x1 * wf.w;
  gg.x += x0 * wg.x + x1 * wg.y;  gg.y += x0 * wg.z + x1 * wg.w;
  go.x += x0 * wo.x + x1 * wo.y;  go.y += x0 * wo.z + x1 * wo.w;
  size_t cbase = (size_t)b * NHD + jp;
  float2 c = *(const float2*)(g_cd + cbase);
  float c20 = sigf(gf.x) * c.x + sigf(gi.x) * tanhfast(gg.x);
  float c21 = sigf(gf.y) * c.y + sigf(gi.y) * tanhfast(gg.y);
  float h20 = sigf(go.x) * tanhfast(c20);
  float h21 = sigf(go.y) * tanhfast(c21);
  *(float2*)(g_cd + cbase) = make_float2(c20, c21);
  size_t ho = ((size_t)b * NT + t) * NHD + jp;
  __nv_bfloat16 hh0, hl0, hh1, hl1;
  split_bf16(h20, &hh0, &hl0);
  split_bf16(h21, &hh1, &hl1);
  *(__nv_bfloat162*)(g_hs_hi + ho) = __nv_bfloat162(hh0, hh1);
  *(__nv_bfloat162*)(g_hs_lo + ho) = __nv_bfloat162(hl0, hl1);
}

// ---------------- PDL launch helper ----------------
template <typename F, typename... Args>
static inline void pdl_launch(F* f, dim3 grid, dim3 block, size_t smem, Args... args) {
  cudaLaunchConfig_t cfg = {};
  cfg.gridDim = grid;
  cfg.blockDim = block;
  cfg.dynamicSmemBytes = smem;
  cfg.stream = 0;
  cudaLaunchAttribute at[1];
  at[0].id = cudaLaunchAttributeProgrammaticStreamSerialization;
  at[0].val.programmaticStreamSerializationAllowed = 1;
  cfg.attrs = at;
  cfg.numAttrs = 1;
  cudaLaunchKernelEx(&cfg, f, args...);
}

static inline void run_gemm(const GArg& a0, const GArg& a1, size_t lda, size_t ldc,
                            int N, int K, int M, int nz) {
  dim3 grid((unsigned)((N + 127) / 128), (unsigned)(M / 128), (unsigned)nz);
  pdl_launch(gemm3<128>, grid, dim3(256), (size_t)GS128, a0, a1, lda, ldc, N, K);
}

extern "C" void kernel_launch(void* const* d_in, const int* in_sizes, int n_in,
                              void* d_out, int out_size) {
  const float* data      = (const float*)d_in[0];
  const float* eps       = (const float*)d_in[1];
  const float* enc_Wih_f = (const float*)d_in[2];
  const float* enc_Whh_f = (const float*)d_in[3];
  const float* enc_b_f   = (const float*)d_in[4];
  const float* enc_Wih_b = (const float*)d_in[5];
  const float* enc_Whh_b = (const float*)d_in[6];
  const float* enc_b_b   = (const float*)d_in[7];
  const float* enc_out_W = (const float*)d_in[8];
  const float* enc_out_b = (const float*)d_in[9];
  const float* init_W    = (const float*)d_in[10];
  const float* init_b    = (const float*)d_in[11];
  const float* dec_Wih   = (const float*)d_in[12];
  const float* dec_Whh   = (const float*)d_in[13];
  const float* dec_b     = (const float*)d_in[14];
  const float* out_W     = (const float*)d_in[15];
  const float* out_b     = (const float*)d_in[16];
  const int*   lengths   = (const int*)d_in[17];

  float* out    = (float*)d_out;
  float* params = out;
  float* zm_out = out + (size_t)NB * NT * NOUTD;
  float* zl_out = zm_out + (size_t)NB * NT;

  cudaFuncSetAttribute(gemm3<128>, cudaFuncAttributeMaxDynamicSharedMemorySize, GS128);
  cudaFuncSetAttribute(gemm3<256>, cudaFuncAttributeMaxDynamicSharedMemorySize, GS);

#define SYM(p, s) cudaGetSymbolAddress((void**)&p, s)
  __nv_bfloat16 *dWhh_hi, *dWhh_lo, *eWf_hi, *eWf_lo, *eWb_hi, *eWb_lo;
  __nv_bfloat16 *eOut_hi, *eOut_lo, *initW_hi, *initW_lo, *zW_hi, *zW_lo, *outW_hi, *outW_lo;
  __nv_bfloat16 *hn_hi, *hn_lo, *z_hi, *z_lo, *h0_hi, *h0_lo, *hs_hi, *hs_lo;
  float *Ge, *zml, *initb, *zp, *G;
  SYM(dWhh_hi, g_dWhh_hi); SYM(dWhh_lo, g_dWhh_lo);
  SYM(eWf_hi, g_eWf_hi); SYM(eWf_lo, g_eWf_lo);
  SYM(eWb_hi, g_eWb_hi); SYM(eWb_lo, g_eWb_lo);
  SYM(eOut_hi, g_eOut_hi); SYM(eOut_lo, g_eOut_lo);
  SYM(initW_hi, g_initW_hi); SYM(initW_lo, g_initW_lo);
  SYM(zW_hi, g_zW_hi); SYM(zW_lo, g_zW_lo);
  SYM(outW_hi, g_outW_hi); SYM(outW_lo, g_outW_lo);
  SYM(hn_hi, g_hn_hi); SYM(hn_lo, g_hn_lo);
  SYM(z_hi, g_z_hi); SYM(z_lo, g_z_lo);
  SYM(h0_hi, g_h0_hi); SYM(h0_lo, g_h0_lo);
  SYM(hs_hi, g_hs_hi); SYM(hs_lo, g_hs_lo);
  SYM(Ge, g_Ge); SYM(zml, g_zml); SYM(initb, g_init); SYM(zp, g_zp); SYM(G, g_G);
#undef SYM

  cvt_all<<<(unsigned)((SEG8 + 255) / 256), 256>>>(
      dec_Whh, enc_Whh_f, enc_Whh_b, enc_out_W, init_W, dec_Wih, out_W);

  // ---- bidirectional encoder, 128 steps (TN=128, S=4, LOOK=2) ----
  for (int t = 0; t < NT; t++) {
    GArg f = {hn_hi, hn_lo, eWf_hi, eWf_lo, enc_b_f, nullptr, Ge};
    GArg bw = {hn_hi + NHE, hn_lo + NHE, eWb_hi, eWb_lo, enc_b_b, nullptr,
               Ge + (size_t)NB * NGE};
    run_gemm(f, bw, 2 * NHE, NGE, NGE, NHE, NB, 2);
    pdl_launch(enc_gate_kernel, dim3(2048), dim3(256), (size_t)0,
               data, lengths, enc_Wih_f, enc_Wih_b, t);
  }

  // ---- latent ----
  {
    GArg a = {hn_hi, hn_lo, eOut_hi, eOut_lo, enc_out_b, nullptr, zml};
    run_gemm(a, a, 2 * NHE, 2 * NZ, 2 * NZ, 2 * NHE, NB, 1);
  }
  pdl_launch(latent_kernel, dim3(256), dim3(256), (size_t)0, eps, zm_out, zl_out);
  {
    GArg a = {z_hi, z_lo, initW_hi, initW_lo, init_b, nullptr, initb};
    run_gemm(a, a, NZ, 2 * NHD, 2 * NHD, NZ, NB, 1);
  }
  pdl_launch(initsplit_kernel, dim3(4096), dim3(256), (size_t)0);
  {
    GArg a = {z_hi, z_lo, zW_hi, zW_lo, dec_b, nullptr, zp};
    run_gemm(a, a, NZ, NGD, NGD, NZ, NB, 1);
  }

  // ---- decoder, 128 steps (TN=256, S=4, LOOK=2 + gate) ----
  for (int t = 0; t < NT; t++) {
    const __nv_bfloat16* Ah = t ? (hs_hi + (size_t)(t - 1) * NHD) : h0_hi;
    const __nv_bfloat16* Al = t ? (hs_lo + (size_t)(t - 1) * NHD) : h0_lo;
    size_t lda = t ? (size_t)NT * NHD : (size_t)NHD;
    GArg a = {Ah, Al, dWhh_hi, dWhh_lo, nullptr, zp, G};
    pdl_launch(gemm3<256>, dim3(32, 4), dim3(256), (size_t)GS,
               a, a, lda, (size_t)NGD, NGD, NHD);
    pdl_launch(dec_gate_kernel, dim3(2048), dim3(256), (size_t)0, data, t);
  }

  // ---- output projection ----
  {
    GArg a = {hs_hi, hs_lo, outW_hi, outW_lo, out_b, nullptr, params};
    run_gemm(a, a, NHD, NOUTD, NOUTD, NHD, NB * NT, 1);
  }
}